// round 12
// baseline (speedup 1.0000x reference)
#include <cuda_runtime.h>
#include <cuda_fp16.h>
#include <cstdint>

// Problem constants
#define B_    128
#define A_    30
#define T_    65
#define FIN_  4
#define H_    1920
#define G4_   7680
#define NSTEP 64

// GEMM tiling: CTA tile 128(M) x 64(N), K chunk = 64 fp16
#define KCHUNKS  30                 // 1920/64 per phase
#define NSTG     4                  // pipeline stages
#define STAGE_B  24576              // A 16K + W 8K
#define SMEMB    (1024 + 1024 + NSTG * STAGE_B)
#define LOFF     14745600u          // per-layer elems in tiled LSTM weights
#define NTHR     256

// ---------------- device scratch (no allocation allowed) ----------------
__device__ __align__(1024) __half g_wih[2u*7680u*1920u];
__device__ __align__(1024) __half g_whh[2u*7680u*1920u];
__device__ __align__(1024) __half g_w3[1920u*1920u];
__device__ __align__(1024) __half g_x[245760];     // 30 chunks x 8192 (128 rows x 64 k)
__device__ __align__(1024) __half g_h0[245760];
__device__ __align__(1024) __half g_h1[245760];
__device__ float g_c[2 * B_ * H_];
__device__ float g_gates[B_ * G4_];
__device__ float g_r3[3 * B_ * H_];                // W3 split-K disjoint slices
__device__ unsigned g_bar[4];                      // [0,1]=cnt/gen for 120-grid, [2,3]=for 90-grid

// ---------------- PTX helpers ----------------
__device__ __forceinline__ uint32_t smem_u32(const void* p) {
    uint32_t a;
    asm("{ .reg .u64 t; cvta.to.shared.u64 t, %1; cvt.u32.u64 %0, t; }" : "=r"(a) : "l"(p));
    return a;
}
#define MBAR_INIT(addr, cnt) \
    asm volatile("mbarrier.init.shared.b64 [%0], %1;" :: "r"(addr), "r"((uint32_t)(cnt)) : "memory")
#define MBAR_EXPECT_TX(addr, bytes) \
    asm volatile("mbarrier.arrive.expect_tx.shared.b64 _, [%0], %1;" :: "r"(addr), "r"((uint32_t)(bytes)) : "memory")
#define MBAR_ARRIVE(addr) \
    asm volatile("mbarrier.arrive.shared.b64 _, [%0];" :: "r"(addr) : "memory")
#define MBAR_WAIT(addr, par) do { \
    uint32_t _m=(addr), _p=(par), _d; \
    asm volatile("{\n\t.reg .pred p;\n\tmbarrier.try_wait.parity.acquire.cta.shared::cta.b64 p, [%1], %2;\n\tselp.b32 %0,1,0,p;\n\t}" \
        : "=r"(_d) : "r"(_m), "r"(_p) : "memory"); \
    if (!_d) { \
        asm volatile("{\n\t.reg .pred P1;\n\tWL_%=:\n\tmbarrier.try_wait.parity.acquire.cta.shared::cta.b64 P1, [%0], %1, 0x989680;\n\t@P1 bra.uni WD_%=;\n\tbra.uni WL_%=;\n\tWD_%=:\n\t}" \
            :: "r"(_m), "r"(_p) : "memory"); \
    } } while (0)
#define BULK_G2S(dst, src, bytes, mbar) \
    asm volatile("cp.async.bulk.shared::cluster.global.mbarrier::complete_tx::bytes [%0], [%1], %2, [%3];" \
        :: "r"(dst), "l"(src), "r"((uint32_t)(bytes)), "r"(mbar) : "memory")

#define LDSM4(r, addr) \
    asm volatile("ldmatrix.sync.aligned.m8n8.x4.shared.b16 {%0,%1,%2,%3}, [%4];" \
        : "=r"((r)[0]), "=r"((r)[1]), "=r"((r)[2]), "=r"((r)[3]) : "r"(addr))
#define MMA(d, a, b0v, b1v) \
    asm volatile("mma.sync.aligned.m16n8k16.row.col.f32.f16.f16.f32 " \
        "{%0,%1,%2,%3}, {%4,%5,%6,%7}, {%8,%9}, {%0,%1,%2,%3};" \
        : "+f"((d)[0]), "+f"((d)[1]), "+f"((d)[2]), "+f"((d)[3]) \
        : "r"((a)[0]), "r"((a)[1]), "r"((a)[2]), "r"((a)[3]), "r"(b0v), "r"(b1v))

__device__ __forceinline__ uint32_t sw128(uint32_t o) { return o ^ ((o >> 3) & 0x70); }
__device__ __forceinline__ uint32_t act_idx(int row, int k) {
    return (uint32_t)((k >> 6) * 8192) + (sw128((uint32_t)(row * 128 + (k & 63) * 2)) >> 1);
}

// ---------------- grid-wide sync over this kernel's co-resident grid ----------------
__device__ __forceinline__ void gsync(unsigned* cnt, unsigned* gen, unsigned n) {
    __syncthreads();
    __threadfence();
    if (threadIdx.x == 0) {
        volatile unsigned* vg = gen;
        unsigned g = *vg;
        if (atomicAdd(cnt, 1u) == n - 1u) {
            *(volatile unsigned*)cnt = 0;
            __threadfence();
            *vg = g + 1u;
        } else {
            while (*vg == g) __nanosleep(32);
        }
        __threadfence();
    }
    __syncthreads();
    asm volatile("fence.proxy.async;" ::: "memory");
}

// ---------------- weight conversion: fp32 [N,1920] -> swizzled fp16 64x64 tiles ----------------
__global__ void __launch_bounds__(256) conv_w(
    const float* __restrict__ src, __half* __restrict__ dst, int total)
{
    int i = blockIdx.x * 256 + threadIdx.x;
    if (i >= total) return;
    int n = i / H_, k = i - n * H_;
    uint32_t d = (uint32_t)((n >> 6) * KCHUNKS + (k >> 6)) * 4096
               + (sw128((uint32_t)((n & 63) * 128 + (k & 63) * 2)) >> 1);
    dst[d] = __float2half(src[i]);
}

// ---------------- GEMM kernel with optional fused LSTM-cell PROLOGUE ----------------
// cell prologue (if cg != null): grid-strided (gates,c) -> c,h; then grid barrier;
// then standard 128x64-tile GEMM: C = sum_ph A_ph @ W_ph^T (+bias).
#define ISSUE_CHUNK(lc, stgA, mbarA) do { \
    int _p = (nph == 2 && (lc) >= KCHUNKS) ? 1 : 0; \
    int _k = (nph == 2) ? ((lc) - _p * KCHUNKS) : (cbeg + (lc)); \
    const __half* _A = (_p ? A1 : A0) + (size_t)_k * 8192; \
    const __half* _W = (_p ? W1 : W0) + ((size_t)nt * KCHUNKS + _k) * 4096; \
    MBAR_EXPECT_TX(mbarA, STAGE_B); \
    BULK_G2S((stgA),         _A, 16384, mbarA); \
    BULK_G2S((stgA) + 16384, _W,  8192, mbarA); \
} while (0)

__global__ void __launch_bounds__(256, 1) gemm_cell(
    float* __restrict__ C, int ldc, int sliceStride,
    const __half* __restrict__ A0, const __half* __restrict__ W0,
    const __half* __restrict__ A1, const __half* __restrict__ W1,
    const float* __restrict__ bias0, const float* __restrict__ bias1,
    int nph, int ccnt, int ntMod,
    const float* __restrict__ cg, float* __restrict__ ccell, __half* __restrict__ hcell,
    unsigned* bcnt, unsigned* bgen, int gridN)
{
    // ---- fused LSTM cell prologue ----
    if (cg) {
        for (int idx = blockIdx.x * NTHR + threadIdx.x; idx < B_ * H_; idx += gridN * NTHR) {
            int b = idx / H_;
            int jj = idx - b * H_;
            const float* g = cg + b * G4_;
            float ig = g[jj], fg = g[H_ + jj], gg = g[2 * H_ + jj], og = g[3 * H_ + jj];
            float si = 1.f / (1.f + expf(-ig));
            float sf = 1.f / (1.f + expf(-fg));
            float so = 1.f / (1.f + expf(-og));
            float tg = tanhf(gg);
            float cn = sf * ccell[idx] + si * tg;
            float hn = so * tanhf(cn);
            ccell[idx] = cn;
            hcell[act_idx(b, jj)] = __float2half(hn);
        }
        gsync(bcnt, bgen, (unsigned)gridN);
    }

    extern __shared__ char smraw[];
    char* sm = (char*)(((unsigned long long)smraw + 1023ull) & ~1023ull);
    const uint32_t sb = smem_u32(sm);
    const uint32_t FULL = sb;
    const uint32_t DONE = sb + 64;
    const uint32_t STG0 = sb + 1024;

    const int tid = threadIdx.x;
    const int wid = tid >> 5, lane = tid & 31;
    int slice, nt;
    if (ntMod) { slice = blockIdx.x / ntMod; nt = blockIdx.x - slice * ntMod; }
    else       { slice = 0; nt = blockIdx.x; }
    const int cbeg = slice * ccnt;
    const int NCH = (nph == 2) ? 2 * KCHUNKS : ccnt;
    const int wm = (wid & 3) * 32;
    const int wn = (wid >> 2) * 32;

    if (tid == 0) {
        for (int s = 0; s < NSTG; s++) { MBAR_INIT(FULL + 8 * s, 1); MBAR_INIT(DONE + 8 * s, 8); }
        asm volatile("fence.proxy.async.shared::cta;" ::: "memory");
    }
    __syncthreads();

    if (tid == 0) {
        for (int c = 0; c < NSTG && c < NCH; c++)
            ISSUE_CHUNK(c, STG0 + c * STAGE_B, FULL + 8 * c);
    }

    float acc[2][4][4];
#pragma unroll
    for (int i = 0; i < 2; i++)
#pragma unroll
        for (int jn = 0; jn < 4; jn++)
#pragma unroll
            for (int q = 0; q < 4; q++) acc[i][jn][q] = 0.f;

    const int a_row  = (lane & 7) + ((lane >> 3) & 1) * 8;
    const int a_koff = (lane >> 4) * 16;
    const int w_row  = (lane & 7) + ((lane >> 4) << 3);
    const int w_koff = ((lane >> 3) & 1) * 16;

    for (int c = 0; c < NCH; c++) {
        int s = c & (NSTG - 1);
        MBAR_WAIT(FULL + 8 * s, (c >> 2) & 1);
        uint32_t stg = STG0 + s * STAGE_B;

#pragma unroll
        for (int kb = 0; kb < 4; kb++) {
            uint32_t av[2][4], wv[2][4];
#pragma unroll
            for (int mt = 0; mt < 2; mt++) {
                uint32_t ad = stg + sw128((uint32_t)((wm + mt * 16 + a_row) * 128 + kb * 32 + a_koff));
                LDSM4(av[mt], ad);
            }
#pragma unroll
            for (int hf = 0; hf < 2; hf++) {
                uint32_t wd = stg + 16384 + sw128((uint32_t)((wn + hf * 16 + w_row) * 128 + kb * 32 + w_koff));
                LDSM4(wv[hf], wd);
            }
#pragma unroll
            for (int mt = 0; mt < 2; mt++) {
#pragma unroll
                for (int hf = 0; hf < 2; hf++) {
                    MMA(acc[mt][2 * hf],     av[mt], wv[hf][0], wv[hf][1]);
                    MMA(acc[mt][2 * hf + 1], av[mt], wv[hf][2], wv[hf][3]);
                }
            }
        }
        __syncwarp();
        if (lane == 0) MBAR_ARRIVE(DONE + 8 * s);

        int ncn = c + NSTG;
        if (tid == 0 && ncn < NCH) {
            MBAR_WAIT(DONE + 8 * s, (c >> 2) & 1);
            ISSUE_CHUNK(ncn, STG0 + s * STAGE_B, FULL + 8 * s);
        }
    }

    // epilogue: lane l holds rows (l>>2, +8), cols 2(l&3), +1 per n8 group
    float* Cb = C + (size_t)slice * sliceStride;
#pragma unroll
    for (int mt = 0; mt < 2; mt++) {
        int r0 = wm + mt * 16 + (lane >> 2);
        float* cp = Cb + (size_t)r0 * ldc;
#pragma unroll
        for (int ng = 0; ng < 4; ng++) {
            int col = nt * 64 + wn + ng * 8 + 2 * (lane & 3);
            float b0v = 0.f, b1v = 0.f;
            if (bias0) { b0v = bias0[col] + bias1[col]; b1v = bias0[col + 1] + bias1[col + 1]; }
            *(float2*)(cp + col) = make_float2(acc[mt][ng][0] + b0v, acc[mt][ng][1] + b1v);
            *(float2*)(cp + 8 * ldc + col) = make_float2(acc[mt][ng][2] + b0v, acc[mt][ng][3] + b1v);
        }
    }
}

// ---------------- tail: sum W3 slices + bias + relu, W4 + residual + out, then MLP ----------------
__global__ void __launch_bounds__(128) tail_kernel(
    const float* __restrict__ r3, const float* __restrict__ b3,
    const float* __restrict__ W4, const float* __restrict__ b4,
    const float* __restrict__ inputs, float* __restrict__ out,
    __half* __restrict__ x,
    const float* __restrict__ W1, const float* __restrict__ b1,
    const float* __restrict__ W2, const float* __restrict__ b2,
    int t, int produce, const int* __restrict__ burn, int do_w4)
{
    __shared__ __align__(16) float xs[H_];
    __shared__ float outs[A_ * FIN_];
    __shared__ float W1t[4 * 64];
    __shared__ float W2t[64 * 64];
    __shared__ float b1s[64], b2s[64];
    __shared__ float ins_s[A_ * FIN_];
    __shared__ float x1s[A_ * 64];

    const int b = blockIdx.x, tid = threadIdx.x;
    const int bi = burn ? *burn : 20;

    if (do_w4) {
        for (int k = tid; k < H_; k += 128)
            xs[k] = fmaxf(r3[b * H_ + k] + r3[(B_ + b) * H_ + k] + r3[(2 * B_ + b) * H_ + k] + b3[k], 0.f);
        __syncthreads();
        if (tid < A_ * FIN_) {
            const float4* wp = (const float4*)(W4 + tid * H_);
            const float4* xp = (const float4*)xs;
            float a0 = 0.f, a1 = 0.f, a2 = 0.f, a3 = 0.f;
#pragma unroll 4
            for (int k = 0; k < H_ / 4; k++) {
                float4 w = wp[k]; float4 xv = xp[k];
                a0 = fmaf(w.x, xv.x, a0); a1 = fmaf(w.y, xv.y, a1);
                a2 = fmaf(w.z, xv.z, a2); a3 = fmaf(w.w, xv.w, a3);
            }
            float acc = b4[tid] + (a0 + a1) + (a2 + a3);
            int a = tid >> 2, f = tid & 3;
            int r = b * A_ + a;
            float insv = (t <= bi) ? inputs[(r * T_ + t) * FIN_ + f]
                                   : out[(r * NSTEP + t - 1) * FIN_ + f];
            float ov = acc + insv;
            out[(r * NSTEP + t) * FIN_ + f] = ov;
            outs[tid] = ov;
        }
        __syncthreads();
    }

    if (produce >= NSTEP) return;

    for (int i = tid; i < 64 * 64; i += 128) {
        int jj = i >> 6, kk = i & 63;
        W2t[kk * 64 + jj] = W2[i];
    }
    for (int i = tid; i < 256; i += 128) {
        int jj = i >> 2, ff = i & 3;
        W1t[ff * 64 + jj] = W1[i];
    }
    if (tid < 64) { b1s[tid] = b1[tid]; b2s[tid] = b2[tid]; }
    if (tid < A_ * FIN_) {
        int a = tid >> 2, f = tid & 3;
        int r = b * A_ + a;
        ins_s[tid] = (produce <= bi) ? inputs[(r * T_ + produce) * FIN_ + f] : outs[tid];
    }
    __syncthreads();

    for (int idx = tid; idx < A_ * 64; idx += 128) {
        int a = idx >> 6, j = idx & 63;
        float v = b1s[j];
#pragma unroll
        for (int f = 0; f < 4; f++) v = fmaf(ins_s[a * 4 + f], W1t[f * 64 + j], v);
        x1s[idx] = fmaxf(v, 0.f);
    }
    __syncthreads();

    for (int idx = tid; idx < A_ * 64; idx += 128) {
        int a = idx >> 6, j = idx & 63;
        float v = b2s[j];
        const float* x1p = x1s + a * 64;
#pragma unroll
        for (int k = 0; k < 64; k++) v = fmaf(x1p[k], W2t[k * 64 + j], v);
        v = fmaxf(v, 0.f);
        x[act_idx(b, a * 64 + j)] = __float2half(v);
    }
}

// ---------------- launch ----------------
extern "C" void kernel_launch(void* const* d_in, const int* in_sizes, int n_in,
                              void* d_out, int out_size)
{
    const float* inputs = (const float*)d_in[0];
    const float* W1  = (const float*)d_in[1];
    const float* b1  = (const float*)d_in[2];
    const float* W2  = (const float*)d_in[3];
    const float* b2  = (const float*)d_in[4];
    const float* Wih = (const float*)d_in[5];
    const float* Whh = (const float*)d_in[6];
    const float* bih = (const float*)d_in[7];
    const float* bhh = (const float*)d_in[8];
    const float* W3  = (const float*)d_in[9];
    const float* b3  = (const float*)d_in[10];
    const float* W4  = (const float*)d_in[11];
    const float* b4  = (const float*)d_in[12];
    const int* burn  = (n_in > 14) ? (const int*)d_in[14] : nullptr;
    float* out = (float*)d_out;

    cudaFuncSetAttribute(gemm_cell, cudaFuncAttributeMaxDynamicSharedMemorySize, SMEMB);

    void *pwih, *pwhh, *pw3, *px, *ph0, *ph1, *pc, *pg, *pr, *pb;
    cudaGetSymbolAddress(&pwih, g_wih);
    cudaGetSymbolAddress(&pwhh, g_whh);
    cudaGetSymbolAddress(&pw3, g_w3);
    cudaGetSymbolAddress(&px, g_x);
    cudaGetSymbolAddress(&ph0, g_h0);
    cudaGetSymbolAddress(&ph1, g_h1);
    cudaGetSymbolAddress(&pc, g_c);
    cudaGetSymbolAddress(&pg, g_gates);
    cudaGetSymbolAddress(&pr, g_r3);
    cudaGetSymbolAddress(&pb, g_bar);

    __half *wih = (__half*)pwih, *whh = (__half*)pwhh, *w3 = (__half*)pw3;
    __half *x = (__half*)px, *h0 = (__half*)ph0, *h1 = (__half*)ph1;
    float* c0 = (float*)pc;  float* c1 = c0 + B_ * H_;
    float* gates = (float*)pg;
    float* r3 = (float*)pr;
    unsigned* bar = (unsigned*)pb;

    // zero recurrent + barrier state (in-graph: deterministic across replays)
    cudaMemsetAsync(pc, 0, sizeof(float) * 2 * B_ * H_);
    cudaMemsetAsync(ph0, 0, sizeof(__half) * 245760);
    cudaMemsetAsync(ph1, 0, sizeof(__half) * 245760);
    cudaMemsetAsync(pb, 0, sizeof(unsigned) * 4);

    // convert weights to pre-swizzled fp16 tiles (once per launch)
    const int TOT_IH = 2 * G4_ * H_;
    const int TOT_W3 = H_ * H_;
    conv_w<<<(TOT_IH + 255) / 256, 256>>>(Wih, wih, TOT_IH);
    conv_w<<<(TOT_IH + 255) / 256, 256>>>(Whh, whh, TOT_IH);
    conv_w<<<(TOT_W3 + 255) / 256, 256>>>(W3, w3, TOT_W3);

    // initial MLP (produce x for t=0)
    tail_kernel<<<B_, 128>>>(r3, b3, W4, b4, inputs, out, x,
                             W1, b1, W2, b2, 0, 0, burn, 0);

    for (int t = 0; t < NSTEP; t++) {
        // K_A: gates0 = x@Wih0^T + h0@Whh0^T + biases (no cell)
        gemm_cell<<<120, NTHR, SMEMB>>>(gates, G4_, 0,
            x, wih, h0, whh, bih, bhh, 2, 0, 0,
            nullptr, nullptr, nullptr, nullptr, nullptr, 0);

        // K_B: cell0 (gates0,c0 -> h0) then gates1 = h0@Wih1^T + h1@Whh1^T + biases
        gemm_cell<<<120, NTHR, SMEMB>>>(gates, G4_, 0,
            h0, wih + LOFF, h1, whh + LOFF, bih + G4_, bhh + G4_, 2, 0, 0,
            gates, c0, h0, bar + 0, bar + 1, 120);

        // K_W3: cell1 (gates1,c1 -> h1) then r3 slices = h1@W3^T (split-K=3, 90 CTAs)
        gemm_cell<<<90, NTHR, SMEMB>>>(r3, H_, B_ * H_,
            h1, w3, nullptr, nullptr, nullptr, nullptr, 1, 10, 30,
            gates, c1, h1, bar + 2, bar + 3, 90);

        // tail: slice-sum + bias/relu + W4 + residual + out, then MLP for t+1
        tail_kernel<<<B_, 128>>>(r3, b3, W4, b4, inputs, out, x,
                                 W1, b1, W2, b2, t, t + 1, burn, 1);
    }
}

// round 13
// speedup vs baseline: 1.1701x; 1.1701x over previous
#include <cuda_runtime.h>
#include <cuda_fp16.h>
#include <cstdint>

// Problem constants
#define B_    128
#define A_    30
#define T_    65
#define FIN_  4
#define H_    1920
#define G4_   7680
#define NSTEP 64

// GEMM tiling: CTA tile 128(M) x 64(N), K chunk = 64 fp16
#define KCHUNKS  30                 // K chunks over full 1920
#define NSTG     4                  // pipeline stages
#define STAGE_B  24576              // A 16K + W 8K
#define SMEMB    (1024 + 1024 + NSTG * STAGE_B)
#define LOFF     14745600u          // per-layer elems in tiled LSTM weights
#define GSLICE   (B_ * G4_)         // one gates slice (floats)

// ---------------- device scratch (no allocation allowed) ----------------
__device__ __align__(1024) __half g_wih[2u*7680u*1920u];
__device__ __align__(1024) __half g_whh[2u*7680u*1920u];
__device__ __align__(1024) __half g_w3[1920u*1920u];
__device__ __align__(1024) __half g_x[245760];     // 30 chunks x 8192 (128 rows x 64 k)
__device__ __align__(1024) __half g_h0[245760];
__device__ __align__(1024) __half g_h1[245760];
__device__ float g_c[2 * B_ * H_];
__device__ float g_gx[GSLICE];                     // x-part of gates (with biases)
__device__ float g_gh0[2 * GSLICE];                // h0@Whh0, 2 K-slices
__device__ float g_gh1[2 * GSLICE];                // h1@Whh1, 2 K-slices
__device__ float g_r3[2 * B_ * H_];                // h1@W3, 2 K-slices

// ---------------- PTX helpers ----------------
__device__ __forceinline__ uint32_t smem_u32(const void* p) {
    uint32_t a;
    asm("{ .reg .u64 t; cvta.to.shared.u64 t, %1; cvt.u32.u64 %0, t; }" : "=r"(a) : "l"(p));
    return a;
}
#define MBAR_INIT(addr, cnt) \
    asm volatile("mbarrier.init.shared.b64 [%0], %1;" :: "r"(addr), "r"((uint32_t)(cnt)) : "memory")
#define MBAR_EXPECT_TX(addr, bytes) \
    asm volatile("mbarrier.arrive.expect_tx.shared.b64 _, [%0], %1;" :: "r"(addr), "r"((uint32_t)(bytes)) : "memory")
#define MBAR_ARRIVE(addr) \
    asm volatile("mbarrier.arrive.shared.b64 _, [%0];" :: "r"(addr) : "memory")
#define MBAR_WAIT(addr, par) do { \
    uint32_t _m=(addr), _p=(par), _d; \
    asm volatile("{\n\t.reg .pred p;\n\tmbarrier.try_wait.parity.acquire.cta.shared::cta.b64 p, [%1], %2;\n\tselp.b32 %0,1,0,p;\n\t}" \
        : "=r"(_d) : "r"(_m), "r"(_p) : "memory"); \
    if (!_d) { \
        asm volatile("{\n\t.reg .pred P1;\n\tWL_%=:\n\tmbarrier.try_wait.parity.acquire.cta.shared::cta.b64 P1, [%0], %1, 0x989680;\n\t@P1 bra.uni WD_%=;\n\tbra.uni WL_%=;\n\tWD_%=:\n\t}" \
            :: "r"(_m), "r"(_p) : "memory"); \
    } } while (0)
#define BULK_G2S(dst, src, bytes, mbar) \
    asm volatile("cp.async.bulk.shared::cluster.global.mbarrier::complete_tx::bytes [%0], [%1], %2, [%3];" \
        :: "r"(dst), "l"(src), "r"((uint32_t)(bytes)), "r"(mbar) : "memory")

#define LDSM4(r, addr) \
    asm volatile("ldmatrix.sync.aligned.m8n8.x4.shared.b16 {%0,%1,%2,%3}, [%4];" \
        : "=r"((r)[0]), "=r"((r)[1]), "=r"((r)[2]), "=r"((r)[3]) : "r"(addr))
#define MMA(d, a, b0v, b1v) \
    asm volatile("mma.sync.aligned.m16n8k16.row.col.f32.f16.f16.f32 " \
        "{%0,%1,%2,%3}, {%4,%5,%6,%7}, {%8,%9}, {%0,%1,%2,%3};" \
        : "+f"((d)[0]), "+f"((d)[1]), "+f"((d)[2]), "+f"((d)[3]) \
        : "r"((a)[0]), "r"((a)[1]), "r"((a)[2]), "r"((a)[3]), "r"(b0v), "r"(b1v))

__device__ __forceinline__ uint32_t sw128(uint32_t o) { return o ^ ((o >> 3) & 0x70); }
__device__ __forceinline__ uint32_t act_idx(int row, int k) {
    return (uint32_t)((k >> 6) * 8192) + (sw128((uint32_t)(row * 128 + (k & 63) * 2)) >> 1);
}

// ---------------- weight conversion: fp32 [N,1920] -> swizzled fp16 64x64 tiles ----------------
__global__ void __launch_bounds__(256) conv_w(
    const float* __restrict__ src, __half* __restrict__ dst, int total)
{
    int i = blockIdx.x * 256 + threadIdx.x;
    if (i >= total) return;
    int n = i / H_, k = i - n * H_;
    uint32_t d = (uint32_t)((n >> 6) * KCHUNKS + (k >> 6)) * 4096
               + (sw128((uint32_t)((n & 63) * 128 + (k & 63) * 2)) >> 1);
    dst[d] = __float2half(src[i]);
}

// ---------------- GEMM core (device): C[128, nt*64..] += A[:, cbeg..]@W^T over ccnt chunks ----------------
__device__ __forceinline__ void gemm_core(
    float* C, int ldc,
    const __half* A, const __half* W,
    const float* bias0, const float* bias1,
    int ccnt, int cbeg, int nt)
{
    extern __shared__ char smraw[];
    char* sm = (char*)(((unsigned long long)smraw + 1023ull) & ~1023ull);
    const uint32_t sb = smem_u32(sm);
    const uint32_t FULL = sb;
    const uint32_t DONE = sb + 64;
    const uint32_t STG0 = sb + 1024;

    const int tid = threadIdx.x;
    const int wid = tid >> 5, lane = tid & 31;
    const int wm = (wid & 3) * 32;
    const int wn = (wid >> 2) * 32;

    if (tid == 0) {
        for (int s = 0; s < NSTG; s++) { MBAR_INIT(FULL + 8 * s, 1); MBAR_INIT(DONE + 8 * s, 8); }
        asm volatile("fence.proxy.async.shared::cta;" ::: "memory");
    }
    __syncthreads();

    if (tid == 0) {
        for (int c = 0; c < NSTG && c < ccnt; c++) {
            int k = cbeg + c;
            uint32_t st = STG0 + c * STAGE_B;
            MBAR_EXPECT_TX(FULL + 8 * c, STAGE_B);
            BULK_G2S(st,         A + (size_t)k * 8192, 16384, FULL + 8 * c);
            BULK_G2S(st + 16384, W + ((size_t)nt * KCHUNKS + k) * 4096, 8192, FULL + 8 * c);
        }
    }

    float acc[2][4][4];
#pragma unroll
    for (int i = 0; i < 2; i++)
#pragma unroll
        for (int jn = 0; jn < 4; jn++)
#pragma unroll
            for (int q = 0; q < 4; q++) acc[i][jn][q] = 0.f;

    const int a_row  = (lane & 7) + ((lane >> 3) & 1) * 8;
    const int a_koff = (lane >> 4) * 16;
    const int w_row  = (lane & 7) + ((lane >> 4) << 3);
    const int w_koff = ((lane >> 3) & 1) * 16;

    for (int c = 0; c < ccnt; c++) {
        int s = c & (NSTG - 1);
        MBAR_WAIT(FULL + 8 * s, (c >> 2) & 1);
        uint32_t stg = STG0 + s * STAGE_B;

#pragma unroll
        for (int kb = 0; kb < 4; kb++) {
            uint32_t av[2][4], wv[2][4];
#pragma unroll
            for (int mt = 0; mt < 2; mt++) {
                uint32_t ad = stg + sw128((uint32_t)((wm + mt * 16 + a_row) * 128 + kb * 32 + a_koff));
                LDSM4(av[mt], ad);
            }
#pragma unroll
            for (int hf = 0; hf < 2; hf++) {
                uint32_t wd = stg + 16384 + sw128((uint32_t)((wn + hf * 16 + w_row) * 128 + kb * 32 + w_koff));
                LDSM4(wv[hf], wd);
            }
#pragma unroll
            for (int mt = 0; mt < 2; mt++) {
#pragma unroll
                for (int hf = 0; hf < 2; hf++) {
                    MMA(acc[mt][2 * hf],     av[mt], wv[hf][0], wv[hf][1]);
                    MMA(acc[mt][2 * hf + 1], av[mt], wv[hf][2], wv[hf][3]);
                }
            }
        }
        __syncwarp();
        if (lane == 0) MBAR_ARRIVE(DONE + 8 * s);

        int ncn = c + NSTG;
        if (tid == 0 && ncn < ccnt) {
            MBAR_WAIT(DONE + 8 * s, (c >> 2) & 1);
            int k = cbeg + ncn;
            uint32_t st = STG0 + s * STAGE_B;
            MBAR_EXPECT_TX(FULL + 8 * s, STAGE_B);
            BULK_G2S(st,         A + (size_t)k * 8192, 16384, FULL + 8 * s);
            BULK_G2S(st + 16384, W + ((size_t)nt * KCHUNKS + k) * 4096, 8192, FULL + 8 * s);
        }
    }

    // epilogue: lane l holds rows (l>>2, +8), cols 2(l&3), +1 per n8 group
#pragma unroll
    for (int mt = 0; mt < 2; mt++) {
        int r0 = wm + mt * 16 + (lane >> 2);
        float* cp = C + (size_t)r0 * ldc;
#pragma unroll
        for (int ng = 0; ng < 4; ng++) {
            int col = nt * 64 + wn + ng * 8 + 2 * (lane & 3);
            float b0v = 0.f, b1v = 0.f;
            if (bias0) { b0v = bias0[col] + bias1[col]; b1v = bias0[col + 1] + bias1[col + 1]; }
            *(float2*)(cp + col) = make_float2(acc[mt][ng][0] + b0v, acc[mt][ng][1] + b1v);
            *(float2*)(cp + 8 * ldc + col) = make_float2(acc[mt][ng][2] + b0v, acc[mt][ng][3] + b1v);
        }
    }
}

// ---------------- serial GEMM (x-parts): full K, with biases ----------------
__global__ void __launch_bounds__(256, 1) gemm_single(
    float* __restrict__ C, int ldc,
    const __half* __restrict__ A, const __half* __restrict__ W,
    const float* __restrict__ bias0, const float* __restrict__ bias1)
{
    gemm_core(C, ldc, A, W, bias0, bias1, KCHUNKS, 0, blockIdx.x);
}

// ---------------- combo: pooled independent GEMMs, 540 uniform CTAs ----------------
// bid 0..239   : gh0 slices = h0@Whh0   (slice=bid/120, nt=bid%120, 15 chunks)
// bid 240..479 : gh1 slices = h1@Whh1
// bid 480..539 : r3  slices = h1@W3     (slice=(bid-480)/30, nt=%30)
__global__ void __launch_bounds__(256, 1) gemm_combo(
    const __half* __restrict__ h0, const __half* __restrict__ h1,
    const __half* __restrict__ whh0, const __half* __restrict__ whh1,
    const __half* __restrict__ w3,
    float* __restrict__ gh0, float* __restrict__ gh1, float* __restrict__ r3,
    int doAux)
{
    int bid = blockIdx.x;
    if (bid < 480) {
        if (!doAux) return;
        int grp = bid / 240;                // 0: gh0, 1: gh1
        int b = bid - grp * 240;
        int slice = b / 120, nt = b - slice * 120;
        float* C = (grp ? gh1 : gh0) + (size_t)slice * GSLICE;
        gemm_core(C, G4_, grp ? h1 : h0, grp ? whh1 : whh0,
                  nullptr, nullptr, 15, slice * 15, nt);
    } else {
        int b = bid - 480;
        int slice = b / 30, nt = b - slice * 30;
        gemm_core(r3 + (size_t)slice * B_ * H_, H_, h1, w3,
                  nullptr, nullptr, 15, slice * 15, nt);
    }
}

// ---------------- LSTM cell: (gx + gh_s0 + gh_s1, c) -> c, h (swizzled fp16) ----------------
__global__ void __launch_bounds__(256) lstm_cell(
    const float* __restrict__ gx, const float* __restrict__ gh,
    float* __restrict__ c, __half* __restrict__ h)
{
    int idx = blockIdx.x * 256 + threadIdx.x;   // < 128*1920
    int b = idx / H_;
    int jj = idx - b * H_;
    const float* px = gx + b * G4_;
    const float* p0 = gh + b * G4_;
    const float* p1 = gh + GSLICE + b * G4_;
    float ig = px[jj]           + p0[jj]           + p1[jj];
    float fg = px[H_ + jj]      + p0[H_ + jj]      + p1[H_ + jj];
    float gg = px[2 * H_ + jj]  + p0[2 * H_ + jj]  + p1[2 * H_ + jj];
    float og = px[3 * H_ + jj]  + p0[3 * H_ + jj]  + p1[3 * H_ + jj];
    float si = 1.f / (1.f + expf(-ig));
    float sf = 1.f / (1.f + expf(-fg));
    float so = 1.f / (1.f + expf(-og));
    float tg = tanhf(gg);
    float cn = sf * c[idx] + si * tg;
    float hn = so * tanhf(cn);
    c[idx] = cn;
    h[act_idx(b, jj)] = __float2half(hn);
}

// ---------------- tail: sum r3 slices + bias + relu, W4 + residual + out, then MLP ----------------
__global__ void __launch_bounds__(128) tail_kernel(
    const float* __restrict__ r3, const float* __restrict__ b3,
    const float* __restrict__ W4, const float* __restrict__ b4,
    const float* __restrict__ inputs, float* __restrict__ out,
    __half* __restrict__ x,
    const float* __restrict__ W1, const float* __restrict__ b1,
    const float* __restrict__ W2, const float* __restrict__ b2,
    int t, int produce, const int* __restrict__ burn, int do_w4)
{
    __shared__ __align__(16) float xs[H_];
    __shared__ float outs[A_ * FIN_];
    __shared__ float W1t[4 * 64];
    __shared__ float W2t[64 * 64];
    __shared__ float b1s[64], b2s[64];
    __shared__ float ins_s[A_ * FIN_];
    __shared__ float x1s[A_ * 64];

    const int b = blockIdx.x, tid = threadIdx.x;
    const int bi = burn ? *burn : 20;

    if (do_w4) {
        for (int k = tid; k < H_; k += 128)
            xs[k] = fmaxf(r3[b * H_ + k] + r3[(B_ + b) * H_ + k] + b3[k], 0.f);
        __syncthreads();
        if (tid < A_ * FIN_) {
            const float4* wp = (const float4*)(W4 + tid * H_);
            const float4* xp = (const float4*)xs;
            float a0 = 0.f, a1 = 0.f, a2 = 0.f, a3 = 0.f;
#pragma unroll 4
            for (int k = 0; k < H_ / 4; k++) {
                float4 w = wp[k]; float4 xv = xp[k];
                a0 = fmaf(w.x, xv.x, a0); a1 = fmaf(w.y, xv.y, a1);
                a2 = fmaf(w.z, xv.z, a2); a3 = fmaf(w.w, xv.w, a3);
            }
            float acc = b4[tid] + (a0 + a1) + (a2 + a3);
            int a = tid >> 2, f = tid & 3;
            int r = b * A_ + a;
            float insv = (t <= bi) ? inputs[(r * T_ + t) * FIN_ + f]
                                   : out[(r * NSTEP + t - 1) * FIN_ + f];
            float ov = acc + insv;
            out[(r * NSTEP + t) * FIN_ + f] = ov;
            outs[tid] = ov;
        }
        __syncthreads();
    }

    if (produce >= NSTEP) return;

    for (int i = tid; i < 64 * 64; i += 128) {
        int jj = i >> 6, kk = i & 63;
        W2t[kk * 64 + jj] = W2[i];
    }
    for (int i = tid; i < 256; i += 128) {
        int jj = i >> 2, ff = i & 3;
        W1t[ff * 64 + jj] = W1[i];
    }
    if (tid < 64) { b1s[tid] = b1[tid]; b2s[tid] = b2[tid]; }
    if (tid < A_ * FIN_) {
        int a = tid >> 2, f = tid & 3;
        int r = b * A_ + a;
        ins_s[tid] = (produce <= bi) ? inputs[(r * T_ + produce) * FIN_ + f] : outs[tid];
    }
    __syncthreads();

    for (int idx = tid; idx < A_ * 64; idx += 128) {
        int a = idx >> 6, j = idx & 63;
        float v = b1s[j];
#pragma unroll
        for (int f = 0; f < 4; f++) v = fmaf(ins_s[a * 4 + f], W1t[f * 64 + j], v);
        x1s[idx] = fmaxf(v, 0.f);
    }
    __syncthreads();

    for (int idx = tid; idx < A_ * 64; idx += 128) {
        int a = idx >> 6, j = idx & 63;
        float v = b2s[j];
        const float* x1p = x1s + a * 64;
#pragma unroll
        for (int k = 0; k < 64; k++) v = fmaf(x1p[k], W2t[k * 64 + j], v);
        v = fmaxf(v, 0.f);
        x[act_idx(b, a * 64 + j)] = __float2half(v);
    }
}

// ---------------- launch ----------------
extern "C" void kernel_launch(void* const* d_in, const int* in_sizes, int n_in,
                              void* d_out, int out_size)
{
    const float* inputs = (const float*)d_in[0];
    const float* W1  = (const float*)d_in[1];
    const float* b1  = (const float*)d_in[2];
    const float* W2  = (const float*)d_in[3];
    const float* b2  = (const float*)d_in[4];
    const float* Wih = (const float*)d_in[5];
    const float* Whh = (const float*)d_in[6];
    const float* bih = (const float*)d_in[7];
    const float* bhh = (const float*)d_in[8];
    const float* W3  = (const float*)d_in[9];
    const float* b3  = (const float*)d_in[10];
    const float* W4  = (const float*)d_in[11];
    const float* b4  = (const float*)d_in[12];
    const int* burn  = (n_in > 14) ? (const int*)d_in[14] : nullptr;
    float* out = (float*)d_out;

    cudaFuncSetAttribute(gemm_single, cudaFuncAttributeMaxDynamicSharedMemorySize, SMEMB);
    cudaFuncSetAttribute(gemm_combo,  cudaFuncAttributeMaxDynamicSharedMemorySize, SMEMB);

    void *pwih, *pwhh, *pw3, *px, *ph0, *ph1, *pc, *pgx, *pgh0, *pgh1, *pr;
    cudaGetSymbolAddress(&pwih, g_wih);
    cudaGetSymbolAddress(&pwhh, g_whh);
    cudaGetSymbolAddress(&pw3, g_w3);
    cudaGetSymbolAddress(&px, g_x);
    cudaGetSymbolAddress(&ph0, g_h0);
    cudaGetSymbolAddress(&ph1, g_h1);
    cudaGetSymbolAddress(&pc, g_c);
    cudaGetSymbolAddress(&pgx, g_gx);
    cudaGetSymbolAddress(&pgh0, g_gh0);
    cudaGetSymbolAddress(&pgh1, g_gh1);
    cudaGetSymbolAddress(&pr, g_r3);

    __half *wih = (__half*)pwih, *whh = (__half*)pwhh, *w3 = (__half*)pw3;
    __half *x = (__half*)px, *h0 = (__half*)ph0, *h1 = (__half*)ph1;
    float* c0 = (float*)pc;  float* c1 = c0 + B_ * H_;
    float* gx = (float*)pgx;
    float* gh0 = (float*)pgh0;
    float* gh1 = (float*)pgh1;
    float* r3 = (float*)pr;

    // zero recurrent state + h-part gates (h=0 at t=0 -> h@Whh = 0)
    cudaMemsetAsync(pc, 0, sizeof(float) * 2 * B_ * H_);
    cudaMemsetAsync(ph0, 0, sizeof(__half) * 245760);
    cudaMemsetAsync(ph1, 0, sizeof(__half) * 245760);
    cudaMemsetAsync(pgh0, 0, sizeof(float) * 2 * GSLICE);
    cudaMemsetAsync(pgh1, 0, sizeof(float) * 2 * GSLICE);

    // convert weights to pre-swizzled fp16 tiles (once per launch)
    const int TOT_IH = 2 * G4_ * H_;
    const int TOT_W3 = H_ * H_;
    conv_w<<<(TOT_IH + 255) / 256, 256>>>(Wih, wih, TOT_IH);
    conv_w<<<(TOT_IH + 255) / 256, 256>>>(Whh, whh, TOT_IH);
    conv_w<<<(TOT_W3 + 255) / 256, 256>>>(W3, w3, TOT_W3);

    // initial MLP (produce x for t=0)
    tail_kernel<<<B_, 128>>>(r3, b3, W4, b4, inputs, out, x,
                             W1, b1, W2, b2, 0, 0, burn, 0);

    for (int t = 0; t < NSTEP; t++) {
        // K_A2: gx = x(t)@Wih0 + biases (h-part precomputed in prior combo)
        gemm_single<<<120, 256, SMEMB>>>(gx, G4_, x, wih, bih, bhh);
        lstm_cell<<<960, 256>>>(gx, gh0, c0, h0);

        // L1a: gx = h0(t)@Wih1 + biases
        gemm_single<<<120, 256, SMEMB>>>(gx, G4_, h0, wih + LOFF, bih + G4_, bhh + G4_);
        lstm_cell<<<960, 256>>>(gx, gh1, c1, h1);

        // combo: pooled {h0@Whh0 -> gh0, h1@Whh1 -> gh1, h1@W3 -> r3}, 540 uniform CTAs
        gemm_combo<<<540, 256, SMEMB>>>(h0, h1, whh, whh + LOFF, w3,
                                        gh0, gh1, r3, t + 1 < NSTEP ? 1 : 0);

        // tail: r3 slice-sum + bias/relu + W4 + residual + out, then MLP for t+1
        tail_kernel<<<B_, 128>>>(r3, b3, W4, b4, inputs, out, x,
                                 W1, b1, W2, b2, t, t + 1, burn, 1);
    }
}

// round 14
// speedup vs baseline: 1.1964x; 1.0225x over previous
#include <cuda_runtime.h>
#include <cuda_fp16.h>
#include <cstdint>

// Problem constants
#define B_    128
#define A_    30
#define T_    65
#define FIN_  4
#define H_    1920
#define G4_   7680
#define NSTEP 64

// GEMM tiling: CTA tile 128(M) x 64(N), K chunk = 64 fp16
#define KCHUNKS  30                 // K chunks over full 1920
#define NSTG     4                  // pipeline stages
#define STAGE_B  24576              // A 16K + W 8K
#define SMEMB    (1024 + 1024 + NSTG * STAGE_B)
#define LOFF     14745600u          // per-layer elems in tiled LSTM weights
#define GSLICE   (B_ * G4_)         // one gates slice (floats)
#define TOT_IH   (2 * G4_ * H_)     // 29,491,200
#define TOT_W3   (H_ * H_)          // 3,686,400

// ---------------- device scratch (no allocation allowed) ----------------
__device__ __align__(1024) __half g_wih[2u*7680u*1920u];
__device__ __align__(1024) __half g_whh[2u*7680u*1920u];
__device__ __align__(1024) __half g_w3[1920u*1920u];
__device__ __align__(1024) __half g_x[245760];     // 30 chunks x 8192 (128 rows x 64 k)
__device__ __align__(1024) __half g_h0[245760];
__device__ __align__(1024) __half g_h1[245760];
__device__ float g_c[2 * B_ * H_];
__device__ float g_gx[GSLICE];                     // x-part of gates (with biases)
__device__ float g_gh0[2 * GSLICE];                // h0@Whh0, 2 K-slices
__device__ float g_gh1[2 * GSLICE];                // h1@Whh1, 2 K-slices
__device__ float g_r3[2 * B_ * H_];                // h1@W3, 2 K-slices

// ---------------- PTX helpers ----------------
__device__ __forceinline__ uint32_t smem_u32(const void* p) {
    uint32_t a;
    asm("{ .reg .u64 t; cvta.to.shared.u64 t, %1; cvt.u32.u64 %0, t; }" : "=r"(a) : "l"(p));
    return a;
}
#define MBAR_INIT(addr, cnt) \
    asm volatile("mbarrier.init.shared.b64 [%0], %1;" :: "r"(addr), "r"((uint32_t)(cnt)) : "memory")
#define MBAR_EXPECT_TX(addr, bytes) \
    asm volatile("mbarrier.arrive.expect_tx.shared.b64 _, [%0], %1;" :: "r"(addr), "r"((uint32_t)(bytes)) : "memory")
#define MBAR_ARRIVE(addr) \
    asm volatile("mbarrier.arrive.shared.b64 _, [%0];" :: "r"(addr) : "memory")
#define MBAR_WAIT(addr, par) do { \
    uint32_t _m=(addr), _p=(par), _d; \
    asm volatile("{\n\t.reg .pred p;\n\tmbarrier.try_wait.parity.acquire.cta.shared::cta.b64 p, [%1], %2;\n\tselp.b32 %0,1,0,p;\n\t}" \
        : "=r"(_d) : "r"(_m), "r"(_p) : "memory"); \
    if (!_d) { \
        asm volatile("{\n\t.reg .pred P1;\n\tWL_%=:\n\tmbarrier.try_wait.parity.acquire.cta.shared::cta.b64 P1, [%0], %1, 0x989680;\n\t@P1 bra.uni WD_%=;\n\tbra.uni WL_%=;\n\tWD_%=:\n\t}" \
            :: "r"(_m), "r"(_p) : "memory"); \
    } } while (0)
#define BULK_G2S(dst, src, bytes, mbar) \
    asm volatile("cp.async.bulk.shared::cluster.global.mbarrier::complete_tx::bytes [%0], [%1], %2, [%3];" \
        :: "r"(dst), "l"(src), "r"((uint32_t)(bytes)), "r"(mbar) : "memory")

#define LDSM4(r, addr) \
    asm volatile("ldmatrix.sync.aligned.m8n8.x4.shared.b16 {%0,%1,%2,%3}, [%4];" \
        : "=r"((r)[0]), "=r"((r)[1]), "=r"((r)[2]), "=r"((r)[3]) : "r"(addr))
#define MMA(d, a, b0v, b1v) \
    asm volatile("mma.sync.aligned.m16n8k16.row.col.f32.f16.f16.f32 " \
        "{%0,%1,%2,%3}, {%4,%5,%6,%7}, {%8,%9}, {%0,%1,%2,%3};" \
        : "+f"((d)[0]), "+f"((d)[1]), "+f"((d)[2]), "+f"((d)[3]) \
        : "r"((a)[0]), "r"((a)[1]), "r"((a)[2]), "r"((a)[3]), "r"(b0v), "r"(b1v))

__device__ __forceinline__ uint32_t sw128(uint32_t o) { return o ^ ((o >> 3) & 0x70); }
__device__ __forceinline__ uint32_t act_idx(int row, int k) {
    return (uint32_t)((k >> 6) * 8192) + (sw128((uint32_t)(row * 128 + (k & 63) * 2)) >> 1);
}

// ---------------- merged weight conversion: all three matrices ----------------
__global__ void __launch_bounds__(256) conv_all(
    const float* __restrict__ Wih, const float* __restrict__ Whh, const float* __restrict__ W3s,
    __half* __restrict__ wih, __half* __restrict__ whh, __half* __restrict__ w3)
{
    int i = blockIdx.x * 256 + threadIdx.x;
    const float* src; __half* dst; int local;
    if (i < TOT_IH)               { src = Wih; dst = wih; local = i; }
    else if (i < 2 * TOT_IH)      { src = Whh; dst = whh; local = i - TOT_IH; }
    else if (i < 2 * TOT_IH + TOT_W3) { src = W3s; dst = w3; local = i - 2 * TOT_IH; }
    else return;
    int n = local / H_, k = local - n * H_;
    uint32_t d = (uint32_t)((n >> 6) * KCHUNKS + (k >> 6)) * 4096
               + (sw128((uint32_t)((n & 63) * 128 + (k & 63) * 2)) >> 1);
    dst[d] = __float2half(src[local]);
}

// ---------------- GEMM core (device) ----------------
__device__ __forceinline__ void gemm_core(
    float* C, int ldc,
    const __half* A, const __half* W,
    const float* bias0, const float* bias1,
    int ccnt, int cbeg, int nt)
{
    extern __shared__ char smraw[];
    char* sm = (char*)(((unsigned long long)smraw + 1023ull) & ~1023ull);
    const uint32_t sb = smem_u32(sm);
    const uint32_t FULL = sb;
    const uint32_t DONE = sb + 64;
    const uint32_t STG0 = sb + 1024;

    const int tid = threadIdx.x;
    const int wid = tid >> 5, lane = tid & 31;
    const int wm = (wid & 3) * 32;
    const int wn = (wid >> 2) * 32;

    if (tid == 0) {
        for (int s = 0; s < NSTG; s++) { MBAR_INIT(FULL + 8 * s, 1); MBAR_INIT(DONE + 8 * s, 8); }
        asm volatile("fence.proxy.async.shared::cta;" ::: "memory");
    }
    __syncthreads();

    // dependency-free prologue done; wait for predecessor before reading activations
    cudaGridDependencySynchronize();

    if (tid == 0) {
        for (int c = 0; c < NSTG && c < ccnt; c++) {
            int k = cbeg + c;
            uint32_t st = STG0 + c * STAGE_B;
            MBAR_EXPECT_TX(FULL + 8 * c, STAGE_B);
            BULK_G2S(st,         A + (size_t)k * 8192, 16384, FULL + 8 * c);
            BULK_G2S(st + 16384, W + ((size_t)nt * KCHUNKS + k) * 4096, 8192, FULL + 8 * c);
        }
    }

    float acc[2][4][4];
#pragma unroll
    for (int i = 0; i < 2; i++)
#pragma unroll
        for (int jn = 0; jn < 4; jn++)
#pragma unroll
            for (int q = 0; q < 4; q++) acc[i][jn][q] = 0.f;

    const int a_row  = (lane & 7) + ((lane >> 3) & 1) * 8;
    const int a_koff = (lane >> 4) * 16;
    const int w_row  = (lane & 7) + ((lane >> 4) << 3);
    const int w_koff = ((lane >> 3) & 1) * 16;

    for (int c = 0; c < ccnt; c++) {
        int s = c & (NSTG - 1);
        MBAR_WAIT(FULL + 8 * s, (c >> 2) & 1);
        uint32_t stg = STG0 + s * STAGE_B;

#pragma unroll
        for (int kb = 0; kb < 4; kb++) {
            uint32_t av[2][4], wv[2][4];
#pragma unroll
            for (int mt = 0; mt < 2; mt++) {
                uint32_t ad = stg + sw128((uint32_t)((wm + mt * 16 + a_row) * 128 + kb * 32 + a_koff));
                LDSM4(av[mt], ad);
            }
#pragma unroll
            for (int hf = 0; hf < 2; hf++) {
                uint32_t wd = stg + 16384 + sw128((uint32_t)((wn + hf * 16 + w_row) * 128 + kb * 32 + w_koff));
                LDSM4(wv[hf], wd);
            }
#pragma unroll
            for (int mt = 0; mt < 2; mt++) {
#pragma unroll
                for (int hf = 0; hf < 2; hf++) {
                    MMA(acc[mt][2 * hf],     av[mt], wv[hf][0], wv[hf][1]);
                    MMA(acc[mt][2 * hf + 1], av[mt], wv[hf][2], wv[hf][3]);
                }
            }
        }
        __syncwarp();
        if (lane == 0) MBAR_ARRIVE(DONE + 8 * s);

        int ncn = c + NSTG;
        if (tid == 0 && ncn < ccnt) {
            MBAR_WAIT(DONE + 8 * s, (c >> 2) & 1);
            int k = cbeg + ncn;
            uint32_t st = STG0 + s * STAGE_B;
            MBAR_EXPECT_TX(FULL + 8 * s, STAGE_B);
            BULK_G2S(st,         A + (size_t)k * 8192, 16384, FULL + 8 * s);
            BULK_G2S(st + 16384, W + ((size_t)nt * KCHUNKS + k) * 4096, 8192, FULL + 8 * s);
        }
    }

#pragma unroll
    for (int mt = 0; mt < 2; mt++) {
        int r0 = wm + mt * 16 + (lane >> 2);
        float* cp = C + (size_t)r0 * ldc;
#pragma unroll
        for (int ng = 0; ng < 4; ng++) {
            int col = nt * 64 + wn + ng * 8 + 2 * (lane & 3);
            float b0v = 0.f, b1v = 0.f;
            if (bias0) { b0v = bias0[col] + bias1[col]; b1v = bias0[col + 1] + bias1[col + 1]; }
            *(float2*)(cp + col) = make_float2(acc[mt][ng][0] + b0v, acc[mt][ng][1] + b1v);
            *(float2*)(cp + 8 * ldc + col) = make_float2(acc[mt][ng][2] + b0v, acc[mt][ng][3] + b1v);
        }
    }
}

// ---------------- serial GEMM (x-parts): full K, with biases ----------------
__global__ void __launch_bounds__(256, 1) gemm_single(
    float* __restrict__ C, int ldc,
    const __half* __restrict__ A, const __half* __restrict__ W,
    const float* __restrict__ bias0, const float* __restrict__ bias1)
{
    gemm_core(C, ldc, A, W, bias0, bias1, KCHUNKS, 0, blockIdx.x);
}

// ---------------- combo: pooled independent GEMMs, 540 uniform CTAs ----------------
__global__ void __launch_bounds__(256, 1) gemm_combo(
    const __half* __restrict__ h0, const __half* __restrict__ h1,
    const __half* __restrict__ whh0, const __half* __restrict__ whh1,
    const __half* __restrict__ w3,
    float* __restrict__ gh0, float* __restrict__ gh1, float* __restrict__ r3,
    int doAux)
{
    int bid = blockIdx.x;
    if (bid < 480) {
        if (!doAux) return;
        int grp = bid / 240;                // 0: gh0, 1: gh1
        int b = bid - grp * 240;
        int slice = b / 120, nt = b - slice * 120;
        float* C = (grp ? gh1 : gh0) + (size_t)slice * GSLICE;
        gemm_core(C, G4_, grp ? h1 : h0, grp ? whh1 : whh0,
                  nullptr, nullptr, 15, slice * 15, nt);
    } else {
        int b = bid - 480;
        int slice = b / 30, nt = b - slice * 30;
        gemm_core(r3 + (size_t)slice * B_ * H_, H_, h1, w3,
                  nullptr, nullptr, 15, slice * 15, nt);
    }
}

// ---------------- LSTM cell: vectorized x4, (gx + gh_s0 + gh_s1, c) -> c, h ----------------
__global__ void __launch_bounds__(256) lstm_cell(
    const float* __restrict__ gx, const float* __restrict__ gh,
    float* __restrict__ c, __half* __restrict__ h)
{
    cudaGridDependencySynchronize();
    int idx4 = (blockIdx.x * 256 + threadIdx.x) * 4;   // < 128*1920, 240 blocks
    int b = idx4 / H_;
    int jj = idx4 - b * H_;                            // jj % 4 == 0
    const float* px = gx + b * G4_;
    const float* p0 = gh + b * G4_;
    const float* p1 = gh + GSLICE + b * G4_;

    float4 xi = *(const float4*)(px + jj),           hi0 = *(const float4*)(p0 + jj),           hi1 = *(const float4*)(p1 + jj);
    float4 xf = *(const float4*)(px + H_ + jj),      hf0 = *(const float4*)(p0 + H_ + jj),      hf1 = *(const float4*)(p1 + H_ + jj);
    float4 xg = *(const float4*)(px + 2 * H_ + jj),  hg0 = *(const float4*)(p0 + 2 * H_ + jj),  hg1 = *(const float4*)(p1 + 2 * H_ + jj);
    float4 xo = *(const float4*)(px + 3 * H_ + jj),  ho0 = *(const float4*)(p0 + 3 * H_ + jj),  ho1 = *(const float4*)(p1 + 3 * H_ + jj);
    float4 cv = *(const float4*)(c + idx4);

    float hn[4], cn[4];
    float igs[4] = { xi.x + hi0.x + hi1.x, xi.y + hi0.y + hi1.y, xi.z + hi0.z + hi1.z, xi.w + hi0.w + hi1.w };
    float fgs[4] = { xf.x + hf0.x + hf1.x, xf.y + hf0.y + hf1.y, xf.z + hf0.z + hf1.z, xf.w + hf0.w + hf1.w };
    float ggs[4] = { xg.x + hg0.x + hg1.x, xg.y + hg0.y + hg1.y, xg.z + hg0.z + hg1.z, xg.w + hg0.w + hg1.w };
    float ogs[4] = { xo.x + ho0.x + ho1.x, xo.y + ho0.y + ho1.y, xo.z + ho0.z + ho1.z, xo.w + ho0.w + ho1.w };
    float cvs[4] = { cv.x, cv.y, cv.z, cv.w };
#pragma unroll
    for (int q = 0; q < 4; q++) {
        float si = 1.f / (1.f + expf(-igs[q]));
        float sf = 1.f / (1.f + expf(-fgs[q]));
        float so = 1.f / (1.f + expf(-ogs[q]));
        float tg = tanhf(ggs[q]);
        cn[q] = sf * cvs[q] + si * tg;
        hn[q] = so * tanhf(cn[q]);
    }
    *(float4*)(c + idx4) = make_float4(cn[0], cn[1], cn[2], cn[3]);

    __half2 a2 = __floats2half2_rn(hn[0], hn[1]);
    __half2 b2 = __floats2half2_rn(hn[2], hn[3]);
    uint32_t byteoff = (uint32_t)(jj >> 6) * 16384 + sw128((uint32_t)(b * 128 + (jj & 63) * 2));
    uint2 v = make_uint2(*(uint32_t*)&a2, *(uint32_t*)&b2);
    *(uint2*)((char*)h + byteoff) = v;
}

// ---------------- tail: static smem staging pre-sync; r3 work post-sync ----------------
__global__ void __launch_bounds__(128) tail_kernel(
    const float* __restrict__ r3, const float* __restrict__ b3,
    const float* __restrict__ W4, const float* __restrict__ b4,
    const float* __restrict__ inputs, float* __restrict__ out,
    __half* __restrict__ x,
    const float* __restrict__ W1, const float* __restrict__ b1,
    const float* __restrict__ W2, const float* __restrict__ b2,
    int t, int produce, const int* __restrict__ burn, int do_w4)
{
    __shared__ __align__(16) float xs[H_];
    __shared__ float outs[A_ * FIN_];
    __shared__ float W1t[4 * 64];
    __shared__ float W2t[64 * 64];
    __shared__ float b1s[64], b2s[64];
    __shared__ float ins_s[A_ * FIN_];
    __shared__ float x1s[A_ * 64];

    const int b = blockIdx.x, tid = threadIdx.x;

    // dependency-free: stage MLP weights (static inputs)
    for (int i = tid; i < 64 * 64; i += 128) {
        int jj = i >> 6, kk = i & 63;
        W2t[kk * 64 + jj] = W2[i];
    }
    for (int i = tid; i < 256; i += 128) {
        int jj = i >> 2, ff = i & 3;
        W1t[ff * 64 + jj] = W1[i];
    }
    if (tid < 64) { b1s[tid] = b1[tid]; b2s[tid] = b2[tid]; }

    cudaGridDependencySynchronize();
    const int bi = burn ? *burn : 20;

    if (do_w4) {
        for (int k = tid; k < H_; k += 128)
            xs[k] = fmaxf(r3[b * H_ + k] + r3[(B_ + b) * H_ + k] + b3[k], 0.f);
        __syncthreads();
        if (tid < A_ * FIN_) {
            const float4* wp = (const float4*)(W4 + tid * H_);
            const float4* xp = (const float4*)xs;
            float a0 = 0.f, a1 = 0.f, a2 = 0.f, a3 = 0.f;
#pragma unroll 4
            for (int k = 0; k < H_ / 4; k++) {
                float4 w = wp[k]; float4 xv = xp[k];
                a0 = fmaf(w.x, xv.x, a0); a1 = fmaf(w.y, xv.y, a1);
                a2 = fmaf(w.z, xv.z, a2); a3 = fmaf(w.w, xv.w, a3);
            }
            float acc = b4[tid] + (a0 + a1) + (a2 + a3);
            int a = tid >> 2, f = tid & 3;
            int r = b * A_ + a;
            float insv = (t <= bi) ? inputs[(r * T_ + t) * FIN_ + f]
                                   : out[(r * NSTEP + t - 1) * FIN_ + f];
            float ov = acc + insv;
            out[(r * NSTEP + t) * FIN_ + f] = ov;
            outs[tid] = ov;
        }
        __syncthreads();
    }

    if (produce >= NSTEP) return;

    if (tid < A_ * FIN_) {
        int a = tid >> 2, f = tid & 3;
        int r = b * A_ + a;
        ins_s[tid] = (produce <= bi) ? inputs[(r * T_ + produce) * FIN_ + f] : outs[tid];
    }
    __syncthreads();

    for (int idx = tid; idx < A_ * 64; idx += 128) {
        int a = idx >> 6, j = idx & 63;
        float v = b1s[j];
#pragma unroll
        for (int f = 0; f < 4; f++) v = fmaf(ins_s[a * 4 + f], W1t[f * 64 + j], v);
        x1s[idx] = fmaxf(v, 0.f);
    }
    __syncthreads();

    for (int idx = tid; idx < A_ * 64; idx += 128) {
        int a = idx >> 6, j = idx & 63;
        float v = b2s[j];
        const float* x1p = x1s + a * 64;
#pragma unroll
        for (int k = 0; k < 64; k++) v = fmaf(x1p[k], W2t[k * 64 + j], v);
        v = fmaxf(v, 0.f);
        x[act_idx(b, a * 64 + j)] = __float2half(v);
    }
}

// ---------------- launch ----------------
extern "C" void kernel_launch(void* const* d_in, const int* in_sizes, int n_in,
                              void* d_out, int out_size)
{
    const float* inputs = (const float*)d_in[0];
    const float* W1  = (const float*)d_in[1];
    const float* b1  = (const float*)d_in[2];
    const float* W2  = (const float*)d_in[3];
    const float* b2  = (const float*)d_in[4];
    const float* Wih = (const float*)d_in[5];
    const float* Whh = (const float*)d_in[6];
    const float* bih = (const float*)d_in[7];
    const float* bhh = (const float*)d_in[8];
    const float* W3  = (const float*)d_in[9];
    const float* b3  = (const float*)d_in[10];
    const float* W4  = (const float*)d_in[11];
    const float* b4  = (const float*)d_in[12];
    const int* burn  = (n_in > 14) ? (const int*)d_in[14] : nullptr;
    float* out = (float*)d_out;

    cudaFuncSetAttribute(gemm_single, cudaFuncAttributeMaxDynamicSharedMemorySize, SMEMB);
    cudaFuncSetAttribute(gemm_combo,  cudaFuncAttributeMaxDynamicSharedMemorySize, SMEMB);

    void *pwih, *pwhh, *pw3, *px, *ph0, *ph1, *pc, *pgx, *pgh0, *pgh1, *pr;
    cudaGetSymbolAddress(&pwih, g_wih);
    cudaGetSymbolAddress(&pwhh, g_whh);
    cudaGetSymbolAddress(&pw3, g_w3);
    cudaGetSymbolAddress(&px, g_x);
    cudaGetSymbolAddress(&ph0, g_h0);
    cudaGetSymbolAddress(&ph1, g_h1);
    cudaGetSymbolAddress(&pc, g_c);
    cudaGetSymbolAddress(&pgx, g_gx);
    cudaGetSymbolAddress(&pgh0, g_gh0);
    cudaGetSymbolAddress(&pgh1, g_gh1);
    cudaGetSymbolAddress(&pr, g_r3);

    __half *wih = (__half*)pwih, *whh = (__half*)pwhh, *w3 = (__half*)pw3;
    __half *x = (__half*)px, *h0 = (__half*)ph0, *h1 = (__half*)ph1;
    float* c0 = (float*)pc;
    float* gx = (float*)pgx;
    float* gh0 = (float*)pgh0;
    float* gh1 = (float*)pgh1;
    float* r3 = (float*)pr;

    // zero recurrent state + h-part gates (h=0 at t=0 -> h@Whh = 0)
    cudaMemsetAsync(pc, 0, sizeof(float) * 2 * B_ * H_);
    cudaMemsetAsync(ph0, 0, sizeof(__half) * 245760);
    cudaMemsetAsync(ph1, 0, sizeof(__half) * 245760);
    cudaMemsetAsync(pgh0, 0, sizeof(float) * 2 * GSLICE);
    cudaMemsetAsync(pgh1, 0, sizeof(float) * 2 * GSLICE);

    // PDL launch config
    cudaLaunchAttribute pdlAttr[1];
    pdlAttr[0].id = cudaLaunchAttributeProgrammaticStreamSerialization;
    pdlAttr[0].val.programmaticStreamSerializationAllowed = 1;
    auto mkcfg = [&](unsigned grid, unsigned block, size_t smem) {
        cudaLaunchConfig_t cfg = {};
        cfg.gridDim = dim3(grid, 1, 1);
        cfg.blockDim = dim3(block, 1, 1);
        cfg.dynamicSmemBytes = smem;
        cfg.stream = 0;
        cfg.attrs = pdlAttr;
        cfg.numAttrs = 1;
        return cfg;
    };

    // convert all weights in one launch
    const int TOTAL_CONV = 2 * TOT_IH + TOT_W3;
    conv_all<<<(TOTAL_CONV + 255) / 256, 256>>>(Wih, Whh, W3, wih, whh, w3);

    // initial MLP (produce x for t=0)
    {
        cudaLaunchConfig_t cfg = mkcfg(B_, 128, 0);
        cudaLaunchKernelEx(&cfg, tail_kernel,
            (const float*)r3, b3, W4, b4, inputs, out, x,
            W1, b1, W2, b2, 0, 0, burn, 0);
    }

    for (int t = 0; t < NSTEP; t++) {
        // K_A2: gx = x(t)@Wih0 + biases
        {
            cudaLaunchConfig_t cfg = mkcfg(120, 256, SMEMB);
            cudaLaunchKernelEx(&cfg, gemm_single, gx, (int)G4_,
                (const __half*)x, (const __half*)wih, bih, bhh);
        }
        {
            cudaLaunchConfig_t cfg = mkcfg(240, 256, 0);
            cudaLaunchKernelEx(&cfg, lstm_cell,
                (const float*)gx, (const float*)gh0, c0, h0);
        }

        // L1a: gx = h0(t)@Wih1 + biases
        {
            cudaLaunchConfig_t cfg = mkcfg(120, 256, SMEMB);
            cudaLaunchKernelEx(&cfg, gemm_single, gx, (int)G4_,
                (const __half*)h0, (const __half*)(wih + LOFF), bih + G4_, bhh + G4_);
        }
        {
            cudaLaunchConfig_t cfg = mkcfg(240, 256, 0);
            cudaLaunchKernelEx(&cfg, lstm_cell,
                (const float*)gx, (const float*)gh1, c0 + B_ * H_, h1);
        }

        // combo: pooled {h0@Whh0, h1@Whh1, h1@W3}
        {
            cudaLaunchConfig_t cfg = mkcfg(540, 256, SMEMB);
            cudaLaunchKernelEx(&cfg, gemm_combo,
                (const __half*)h0, (const __half*)h1,
                (const __half*)whh, (const __half*)(whh + LOFF), (const __half*)w3,
                gh0, gh1, r3, (int)(t + 1 < NSTEP ? 1 : 0));
        }

        // tail: r3 slice-sum + bias/relu + W4 + residual + out, then MLP for t+1
        {
            cudaLaunchConfig_t cfg = mkcfg(B_, 128, 0);
            cudaLaunchKernelEx(&cfg, tail_kernel,
                (const float*)r3, b3, W4, b4, inputs, out, x,
                W1, b1, W2, b2, t, t + 1, burn, 1);
        }
    }
}

// round 15
// speedup vs baseline: 1.4357x; 1.2000x over previous
#include <cuda_runtime.h>
#include <cuda_fp16.h>
#include <cstdint>

// Problem constants
#define B_    128
#define A_    30
#define T_    65
#define FIN_  4
#define H_    1920
#define G4_   7680
#define NSTEP 64

// GEMM tiling: CTA tile 128(M) x 64(N), K chunk = 64 fp16
#define KCHUNKS  30                 // K chunks over full 1920
#define NSTG     4                  // pipeline stages
#define STAGE_B  24576              // A 16K + W 8K
#define SMEMB    (1024 + 1024 + NSTG * STAGE_B)
#define LOFF     14745600u          // per-layer elems in tiled LSTM weights
#define GSLICE   (B_ * G4_)         // one gates slice (floats)
#define TOT_IH   (2 * G4_ * H_)     // 29,491,200
#define TOT_W3   (H_ * H_)          // 3,686,400

// ---------------- device scratch (no allocation allowed) ----------------
__device__ __align__(1024) __half g_wih[2u*7680u*1920u];
__device__ __align__(1024) __half g_whh[2u*7680u*1920u];
__device__ __align__(1024) __half g_w3[1920u*1920u];
__device__ __align__(1024) __half g_x[245760];     // 30 chunks x 8192 (128 rows x 64 k)
__device__ __align__(1024) __half g_h0[245760];
__device__ __align__(1024) __half g_h1[245760];
__device__ float g_c[2 * B_ * H_];
__device__ float g_gx[GSLICE];                     // x@Wih0 (+biases), 1 slice
__device__ float g_gx1[2 * GSLICE];                // h0@Wih1 (+biases on s0), 2 K-slices
__device__ float g_gh0[2 * GSLICE];                // h0@Whh0, 2 K-slices
__device__ float g_gh1[2 * GSLICE];                // h1@Whh1, 2 K-slices
__device__ float g_r3[2 * B_ * H_];                // h1@W3, 2 K-slices

// ---------------- PTX helpers ----------------
__device__ __forceinline__ uint32_t smem_u32(const void* p) {
    uint32_t a;
    asm("{ .reg .u64 t; cvta.to.shared.u64 t, %1; cvt.u32.u64 %0, t; }" : "=r"(a) : "l"(p));
    return a;
}
#define MBAR_INIT(addr, cnt) \
    asm volatile("mbarrier.init.shared.b64 [%0], %1;" :: "r"(addr), "r"((uint32_t)(cnt)) : "memory")
#define MBAR_EXPECT_TX(addr, bytes) \
    asm volatile("mbarrier.arrive.expect_tx.shared.b64 _, [%0], %1;" :: "r"(addr), "r"((uint32_t)(bytes)) : "memory")
#define MBAR_ARRIVE(addr) \
    asm volatile("mbarrier.arrive.shared.b64 _, [%0];" :: "r"(addr) : "memory")
#define MBAR_WAIT(addr, par) do { \
    uint32_t _m=(addr), _p=(par), _d; \
    asm volatile("{\n\t.reg .pred p;\n\tmbarrier.try_wait.parity.acquire.cta.shared::cta.b64 p, [%1], %2;\n\tselp.b32 %0,1,0,p;\n\t}" \
        : "=r"(_d) : "r"(_m), "r"(_p) : "memory"); \
    if (!_d) { \
        asm volatile("{\n\t.reg .pred P1;\n\tWL_%=:\n\tmbarrier.try_wait.parity.acquire.cta.shared::cta.b64 P1, [%0], %1, 0x989680;\n\t@P1 bra.uni WD_%=;\n\tbra.uni WL_%=;\n\tWD_%=:\n\t}" \
            :: "r"(_m), "r"(_p) : "memory"); \
    } } while (0)
#define BULK_G2S(dst, src, bytes, mbar) \
    asm volatile("cp.async.bulk.shared::cluster.global.mbarrier::complete_tx::bytes [%0], [%1], %2, [%3];" \
        :: "r"(dst), "l"(src), "r"((uint32_t)(bytes)), "r"(mbar) : "memory")

#define LDSM4(r, addr) \
    asm volatile("ldmatrix.sync.aligned.m8n8.x4.shared.b16 {%0,%1,%2,%3}, [%4];" \
        : "=r"((r)[0]), "=r"((r)[1]), "=r"((r)[2]), "=r"((r)[3]) : "r"(addr))
#define MMA(d, a, b0v, b1v) \
    asm volatile("mma.sync.aligned.m16n8k16.row.col.f32.f16.f16.f32 " \
        "{%0,%1,%2,%3}, {%4,%5,%6,%7}, {%8,%9}, {%0,%1,%2,%3};" \
        : "+f"((d)[0]), "+f"((d)[1]), "+f"((d)[2]), "+f"((d)[3]) \
        : "r"((a)[0]), "r"((a)[1]), "r"((a)[2]), "r"((a)[3]), "r"(b0v), "r"(b1v))

__device__ __forceinline__ uint32_t sw128(uint32_t o) { return o ^ ((o >> 3) & 0x70); }
__device__ __forceinline__ uint32_t act_idx(int row, int k) {
    return (uint32_t)((k >> 6) * 8192) + (sw128((uint32_t)(row * 128 + (k & 63) * 2)) >> 1);
}

// ---------------- merged weight conversion ----------------
__global__ void __launch_bounds__(256) conv_all(
    const float* __restrict__ Wih, const float* __restrict__ Whh, const float* __restrict__ W3s,
    __half* __restrict__ wih, __half* __restrict__ whh, __half* __restrict__ w3)
{
    int i = blockIdx.x * 256 + threadIdx.x;
    const float* src; __half* dst; int local;
    if (i < TOT_IH)               { src = Wih; dst = wih; local = i; }
    else if (i < 2 * TOT_IH)      { src = Whh; dst = whh; local = i - TOT_IH; }
    else if (i < 2 * TOT_IH + TOT_W3) { src = W3s; dst = w3; local = i - 2 * TOT_IH; }
    else return;
    int n = local / H_, k = local - n * H_;
    uint32_t d = (uint32_t)((n >> 6) * KCHUNKS + (k >> 6)) * 4096
               + (sw128((uint32_t)((n & 63) * 128 + (k & 63) * 2)) >> 1);
    dst[d] = __float2half(src[local]);
}

// ---------------- GEMM core (device) ----------------
__device__ __forceinline__ void gemm_core(
    float* C, int ldc,
    const __half* A, const __half* W,
    const float* bias0, const float* bias1,
    int ccnt, int cbeg, int nt)
{
    extern __shared__ char smraw[];
    char* sm = (char*)(((unsigned long long)smraw + 1023ull) & ~1023ull);
    const uint32_t sb = smem_u32(sm);
    const uint32_t FULL = sb;
    const uint32_t DONE = sb + 64;
    const uint32_t STG0 = sb + 1024;

    const int tid = threadIdx.x;
    const int wid = tid >> 5, lane = tid & 31;
    const int wm = (wid & 3) * 32;
    const int wn = (wid >> 2) * 32;

    if (tid == 0) {
        for (int s = 0; s < NSTG; s++) { MBAR_INIT(FULL + 8 * s, 1); MBAR_INIT(DONE + 8 * s, 8); }
        asm volatile("fence.proxy.async.shared::cta;" ::: "memory");
    }
    __syncthreads();

    cudaGridDependencySynchronize();

    if (tid == 0) {
        for (int c = 0; c < NSTG && c < ccnt; c++) {
            int k = cbeg + c;
            uint32_t st = STG0 + c * STAGE_B;
            MBAR_EXPECT_TX(FULL + 8 * c, STAGE_B);
            BULK_G2S(st,         A + (size_t)k * 8192, 16384, FULL + 8 * c);
            BULK_G2S(st + 16384, W + ((size_t)nt * KCHUNKS + k) * 4096, 8192, FULL + 8 * c);
        }
    }

    float acc[2][4][4];
#pragma unroll
    for (int i = 0; i < 2; i++)
#pragma unroll
        for (int jn = 0; jn < 4; jn++)
#pragma unroll
            for (int q = 0; q < 4; q++) acc[i][jn][q] = 0.f;

    const int a_row  = (lane & 7) + ((lane >> 3) & 1) * 8;
    const int a_koff = (lane >> 4) * 16;
    const int w_row  = (lane & 7) + ((lane >> 4) << 3);
    const int w_koff = ((lane >> 3) & 1) * 16;

    for (int c = 0; c < ccnt; c++) {
        int s = c & (NSTG - 1);
        MBAR_WAIT(FULL + 8 * s, (c >> 2) & 1);
        uint32_t stg = STG0 + s * STAGE_B;

#pragma unroll
        for (int kb = 0; kb < 4; kb++) {
            uint32_t av[2][4], wv[2][4];
#pragma unroll
            for (int mt = 0; mt < 2; mt++) {
                uint32_t ad = stg + sw128((uint32_t)((wm + mt * 16 + a_row) * 128 + kb * 32 + a_koff));
                LDSM4(av[mt], ad);
            }
#pragma unroll
            for (int hf = 0; hf < 2; hf++) {
                uint32_t wd = stg + 16384 + sw128((uint32_t)((wn + hf * 16 + w_row) * 128 + kb * 32 + w_koff));
                LDSM4(wv[hf], wd);
            }
#pragma unroll
            for (int mt = 0; mt < 2; mt++) {
#pragma unroll
                for (int hf = 0; hf < 2; hf++) {
                    MMA(acc[mt][2 * hf],     av[mt], wv[hf][0], wv[hf][1]);
                    MMA(acc[mt][2 * hf + 1], av[mt], wv[hf][2], wv[hf][3]);
                }
            }
        }
        __syncwarp();
        if (lane == 0) MBAR_ARRIVE(DONE + 8 * s);

        int ncn = c + NSTG;
        if (tid == 0 && ncn < ccnt) {
            MBAR_WAIT(DONE + 8 * s, (c >> 2) & 1);
            int k = cbeg + ncn;
            uint32_t st = STG0 + s * STAGE_B;
            MBAR_EXPECT_TX(FULL + 8 * s, STAGE_B);
            BULK_G2S(st,         A + (size_t)k * 8192, 16384, FULL + 8 * s);
            BULK_G2S(st + 16384, W + ((size_t)nt * KCHUNKS + k) * 4096, 8192, FULL + 8 * s);
        }
    }

#pragma unroll
    for (int mt = 0; mt < 2; mt++) {
        int r0 = wm + mt * 16 + (lane >> 2);
        float* cp = C + (size_t)r0 * ldc;
#pragma unroll
        for (int ng = 0; ng < 4; ng++) {
            int col = nt * 64 + wn + ng * 8 + 2 * (lane & 3);
            float b0v = 0.f, b1v = 0.f;
            if (bias0) { b0v = bias0[col] + bias1[col]; b1v = bias0[col + 1] + bias1[col + 1]; }
            *(float2*)(cp + col) = make_float2(acc[mt][ng][0] + b0v, acc[mt][ng][1] + b1v);
            *(float2*)(cp + 8 * ldc + col) = make_float2(acc[mt][ng][2] + b0v, acc[mt][ng][3] + b1v);
        }
    }
}

// ---------------- K_A2: x@Wih0 full-K with biases ----------------
__global__ void __launch_bounds__(256, 1) gemm_single(
    float* __restrict__ C, int ldc,
    const __half* __restrict__ A, const __half* __restrict__ W,
    const float* __restrict__ bias0, const float* __restrict__ bias1)
{
    gemm_core(C, ldc, A, W, bias0, bias1, KCHUNKS, 0, blockIdx.x);
}

// ---------------- comboA: {h0@Wih1 -> gx1 (240), h0@Whh0 -> gh0 (240)}, 480 CTAs x 15ch ----------------
__global__ void __launch_bounds__(256, 1) gemm_comboA(
    const __half* __restrict__ h0,
    const __half* __restrict__ wih1, const __half* __restrict__ whh0,
    float* __restrict__ gx1, float* __restrict__ gh0,
    const float* __restrict__ bih1, const float* __restrict__ bhh1,
    int doGh)
{
    int bid = blockIdx.x;
    if (bid < 240) {
        int slice = bid / 120, nt = bid - slice * 120;
        const float* b0 = (slice == 0) ? bih1 : nullptr;
        const float* b1 = (slice == 0) ? bhh1 : nullptr;
        gemm_core(gx1 + (size_t)slice * GSLICE, G4_, h0, wih1, b0, b1, 15, slice * 15, nt);
    } else {
        if (!doGh) return;
        int b = bid - 240;
        int slice = b / 120, nt = b - slice * 120;
        gemm_core(gh0 + (size_t)slice * GSLICE, G4_, h0, whh0, nullptr, nullptr, 15, slice * 15, nt);
    }
}

// ---------------- comboB: {h1@Whh1 -> gh1 (240), h1@W3 -> r3 (60)}, 300 CTAs x 15ch ----------------
__global__ void __launch_bounds__(256, 1) gemm_comboB(
    const __half* __restrict__ h1,
    const __half* __restrict__ whh1, const __half* __restrict__ w3,
    float* __restrict__ gh1, float* __restrict__ r3, int doGh)
{
    int bid = blockIdx.x;
    if (bid < 240) {
        if (!doGh) return;
        int slice = bid / 120, nt = bid - slice * 120;
        gemm_core(gh1 + (size_t)slice * GSLICE, G4_, h1, whh1, nullptr, nullptr, 15, slice * 15, nt);
    } else {
        int b = bid - 240;
        int slice = b / 30, nt = b - slice * 30;
        gemm_core(r3 + (size_t)slice * B_ * H_, H_, h1, w3, nullptr, nullptr, 15, slice * 15, nt);
    }
}

// ---------------- LSTM cell: vectorized x4; sums 1-2 gx slices + 2 gh slices ----------------
__global__ void __launch_bounds__(256) lstm_cell(
    const float* __restrict__ gx, const float* __restrict__ gh,
    float* __restrict__ c, __half* __restrict__ h, int twoGx)
{
    cudaGridDependencySynchronize();
    int idx4 = (blockIdx.x * 256 + threadIdx.x) * 4;   // < 128*1920, 240 blocks
    int b = idx4 / H_;
    int jj = idx4 - b * H_;
    const float* px = gx + b * G4_;
    const float* px2 = gx + GSLICE + b * G4_;
    const float* p0 = gh + b * G4_;
    const float* p1 = gh + GSLICE + b * G4_;

    float igs[4], fgs[4], ggs[4], ogs[4];
    {
        float4 xi = *(const float4*)(px + jj),           hi0 = *(const float4*)(p0 + jj),           hi1 = *(const float4*)(p1 + jj);
        float4 xf = *(const float4*)(px + H_ + jj),      hf0 = *(const float4*)(p0 + H_ + jj),      hf1 = *(const float4*)(p1 + H_ + jj);
        float4 xg = *(const float4*)(px + 2 * H_ + jj),  hg0 = *(const float4*)(p0 + 2 * H_ + jj),  hg1 = *(const float4*)(p1 + 2 * H_ + jj);
        float4 xo = *(const float4*)(px + 3 * H_ + jj),  ho0 = *(const float4*)(p0 + 3 * H_ + jj),  ho1 = *(const float4*)(p1 + 3 * H_ + jj);
        igs[0] = xi.x + hi0.x + hi1.x; igs[1] = xi.y + hi0.y + hi1.y; igs[2] = xi.z + hi0.z + hi1.z; igs[3] = xi.w + hi0.w + hi1.w;
        fgs[0] = xf.x + hf0.x + hf1.x; fgs[1] = xf.y + hf0.y + hf1.y; fgs[2] = xf.z + hf0.z + hf1.z; fgs[3] = xf.w + hf0.w + hf1.w;
        ggs[0] = xg.x + hg0.x + hg1.x; ggs[1] = xg.y + hg0.y + hg1.y; ggs[2] = xg.z + hg0.z + hg1.z; ggs[3] = xg.w + hg0.w + hg1.w;
        ogs[0] = xo.x + ho0.x + ho1.x; ogs[1] = xo.y + ho0.y + ho1.y; ogs[2] = xo.z + ho0.z + ho1.z; ogs[3] = xo.w + ho0.w + ho1.w;
    }
    if (twoGx) {
        float4 xi = *(const float4*)(px2 + jj);
        float4 xf = *(const float4*)(px2 + H_ + jj);
        float4 xg = *(const float4*)(px2 + 2 * H_ + jj);
        float4 xo = *(const float4*)(px2 + 3 * H_ + jj);
        igs[0] += xi.x; igs[1] += xi.y; igs[2] += xi.z; igs[3] += xi.w;
        fgs[0] += xf.x; fgs[1] += xf.y; fgs[2] += xf.z; fgs[3] += xf.w;
        ggs[0] += xg.x; ggs[1] += xg.y; ggs[2] += xg.z; ggs[3] += xg.w;
        ogs[0] += xo.x; ogs[1] += xo.y; ogs[2] += xo.z; ogs[3] += xo.w;
    }
    float4 cv = *(const float4*)(c + idx4);
    float cvs[4] = { cv.x, cv.y, cv.z, cv.w };
    float hn[4], cn[4];
#pragma unroll
    for (int q = 0; q < 4; q++) {
        float si = 1.f / (1.f + expf(-igs[q]));
        float sf = 1.f / (1.f + expf(-fgs[q]));
        float so = 1.f / (1.f + expf(-ogs[q]));
        float tg = tanhf(ggs[q]);
        cn[q] = sf * cvs[q] + si * tg;
        hn[q] = so * tanhf(cn[q]);
    }
    *(float4*)(c + idx4) = make_float4(cn[0], cn[1], cn[2], cn[3]);

    __half2 a2 = __floats2half2_rn(hn[0], hn[1]);
    __half2 b2 = __floats2half2_rn(hn[2], hn[3]);
    uint32_t byteoff = (uint32_t)(jj >> 6) * 16384 + sw128((uint32_t)(b * 128 + (jj & 63) * 2));
    *(uint2*)((char*)h + byteoff) = make_uint2(*(uint32_t*)&a2, *(uint32_t*)&b2);
}

// ---------------- tail (256 thr): r3 sum + W4 (split dots) + residual + out, then MLP ----------------
__global__ void __launch_bounds__(256) tail_kernel(
    const float* __restrict__ r3, const float* __restrict__ b3,
    const float* __restrict__ W4, const float* __restrict__ b4,
    const float* __restrict__ inputs, float* __restrict__ out,
    __half* __restrict__ x,
    const float* __restrict__ W1, const float* __restrict__ b1,
    const float* __restrict__ W2, const float* __restrict__ b2,
    int t, int produce, const int* __restrict__ burn, int do_w4)
{
    __shared__ __align__(16) float xs[H_];
    __shared__ float part[240];
    __shared__ float outs[A_ * FIN_];
    __shared__ float W1t[4 * 64];
    __shared__ float W2t[64 * 64];
    __shared__ float b1s[64], b2s[64];
    __shared__ float ins_s[A_ * FIN_];
    __shared__ float x1s[A_ * 64];

    const int b = blockIdx.x, tid = threadIdx.x;

    // dependency-free: stage MLP weights
    for (int i = tid; i < 64 * 64; i += 256) {
        int jj = i >> 6, kk = i & 63;
        W2t[kk * 64 + jj] = W2[i];
    }
    if (tid < 256) {
        int jj = tid >> 2, ff = tid & 3;
        W1t[ff * 64 + jj] = W1[tid];
    }
    if (tid < 64) { b1s[tid] = b1[tid]; b2s[tid] = b2[tid]; }

    cudaGridDependencySynchronize();
    const int bi = burn ? *burn : 20;

    if (do_w4) {
        for (int k = tid; k < H_; k += 256)
            xs[k] = fmaxf(r3[b * H_ + k] + r3[(B_ + b) * H_ + k] + b3[k], 0.f);
        __syncthreads();
        if (tid < 240) {
            int o = tid % 120, half = tid / 120;
            const float4* wp = (const float4*)(W4 + (size_t)o * H_ + half * 960);
            const float4* xp = (const float4*)(xs + half * 960);
            float a0 = 0.f, a1 = 0.f, a2 = 0.f, a3 = 0.f;
#pragma unroll 4
            for (int k = 0; k < 240; k++) {
                float4 w = wp[k]; float4 xv = xp[k];
                a0 = fmaf(w.x, xv.x, a0); a1 = fmaf(w.y, xv.y, a1);
                a2 = fmaf(w.z, xv.z, a2); a3 = fmaf(w.w, xv.w, a3);
            }
            part[tid] = (a0 + a1) + (a2 + a3);
        }
        __syncthreads();
        if (tid < A_ * FIN_) {
            float acc = b4[tid] + part[tid] + part[tid + 120];
            int a = tid >> 2, f = tid & 3;
            int r = b * A_ + a;
            float insv = (t <= bi) ? inputs[(r * T_ + t) * FIN_ + f]
                                   : out[(r * NSTEP + t - 1) * FIN_ + f];
            float ov = acc + insv;
            out[(r * NSTEP + t) * FIN_ + f] = ov;
            outs[tid] = ov;
        }
        __syncthreads();
    }

    if (produce >= NSTEP) return;

    if (tid < A_ * FIN_) {
        int a = tid >> 2, f = tid & 3;
        int r = b * A_ + a;
        ins_s[tid] = (produce <= bi) ? inputs[(r * T_ + produce) * FIN_ + f] : outs[tid];
    }
    __syncthreads();

    for (int idx = tid; idx < A_ * 64; idx += 256) {
        int a = idx >> 6, j = idx & 63;
        float v = b1s[j];
#pragma unroll
        for (int f = 0; f < 4; f++) v = fmaf(ins_s[a * 4 + f], W1t[f * 64 + j], v);
        x1s[idx] = fmaxf(v, 0.f);
    }
    __syncthreads();

    for (int idx = tid; idx < A_ * 64; idx += 256) {
        int a = idx >> 6, j = idx & 63;
        float v = b2s[j];
        const float* x1p = x1s + a * 64;
#pragma unroll
        for (int k = 0; k < 64; k++) v = fmaf(x1p[k], W2t[k * 64 + j], v);
        v = fmaxf(v, 0.f);
        x[act_idx(b, a * 64 + j)] = __float2half(v);
    }
}

// ---------------- launch ----------------
extern "C" void kernel_launch(void* const* d_in, const int* in_sizes, int n_in,
                              void* d_out, int out_size)
{
    const float* inputs = (const float*)d_in[0];
    const float* W1  = (const float*)d_in[1];
    const float* b1  = (const float*)d_in[2];
    const float* W2  = (const float*)d_in[3];
    const float* b2  = (const float*)d_in[4];
    const float* Wih = (const float*)d_in[5];
    const float* Whh = (const float*)d_in[6];
    const float* bih = (const float*)d_in[7];
    const float* bhh = (const float*)d_in[8];
    const float* W3  = (const float*)d_in[9];
    const float* b3  = (const float*)d_in[10];
    const float* W4  = (const float*)d_in[11];
    const float* b4  = (const float*)d_in[12];
    const int* burn  = (n_in > 14) ? (const int*)d_in[14] : nullptr;
    float* out = (float*)d_out;

    cudaFuncSetAttribute(gemm_single, cudaFuncAttributeMaxDynamicSharedMemorySize, SMEMB);
    cudaFuncSetAttribute(gemm_comboA, cudaFuncAttributeMaxDynamicSharedMemorySize, SMEMB);
    cudaFuncSetAttribute(gemm_comboB, cudaFuncAttributeMaxDynamicSharedMemorySize, SMEMB);

    void *pwih, *pwhh, *pw3, *px, *ph0, *ph1, *pc, *pgx, *pgx1, *pgh0, *pgh1, *pr;
    cudaGetSymbolAddress(&pwih, g_wih);
    cudaGetSymbolAddress(&pwhh, g_whh);
    cudaGetSymbolAddress(&pw3, g_w3);
    cudaGetSymbolAddress(&px, g_x);
    cudaGetSymbolAddress(&ph0, g_h0);
    cudaGetSymbolAddress(&ph1, g_h1);
    cudaGetSymbolAddress(&pc, g_c);
    cudaGetSymbolAddress(&pgx, g_gx);
    cudaGetSymbolAddress(&pgx1, g_gx1);
    cudaGetSymbolAddress(&pgh0, g_gh0);
    cudaGetSymbolAddress(&pgh1, g_gh1);
    cudaGetSymbolAddress(&pr, g_r3);

    __half *wih = (__half*)pwih, *whh = (__half*)pwhh, *w3 = (__half*)pw3;
    __half *x = (__half*)px, *h0 = (__half*)ph0, *h1 = (__half*)ph1;
    float* c0 = (float*)pc;
    float* gx = (float*)pgx;
    float* gx1 = (float*)pgx1;
    float* gh0 = (float*)pgh0;
    float* gh1 = (float*)pgh1;
    float* r3 = (float*)pr;

    // zero recurrent state + h-part gate slices (h=0 at t=0)
    cudaMemsetAsync(pc, 0, sizeof(float) * 2 * B_ * H_);
    cudaMemsetAsync(ph0, 0, sizeof(__half) * 245760);
    cudaMemsetAsync(ph1, 0, sizeof(__half) * 245760);
    cudaMemsetAsync(pgh0, 0, sizeof(float) * 2 * GSLICE);
    cudaMemsetAsync(pgh1, 0, sizeof(float) * 2 * GSLICE);

    // PDL launch config
    cudaLaunchAttribute pdlAttr[1];
    pdlAttr[0].id = cudaLaunchAttributeProgrammaticStreamSerialization;
    pdlAttr[0].val.programmaticStreamSerializationAllowed = 1;
    auto mkcfg = [&](unsigned grid, unsigned block, size_t smem) {
        cudaLaunchConfig_t cfg = {};
        cfg.gridDim = dim3(grid, 1, 1);
        cfg.blockDim = dim3(block, 1, 1);
        cfg.dynamicSmemBytes = smem;
        cfg.stream = 0;
        cfg.attrs = pdlAttr;
        cfg.numAttrs = 1;
        return cfg;
    };

    const int TOTAL_CONV = 2 * TOT_IH + TOT_W3;
    conv_all<<<(TOTAL_CONV + 255) / 256, 256>>>(Wih, Whh, W3, wih, whh, w3);

    // initial MLP (produce x for t=0)
    {
        cudaLaunchConfig_t cfg = mkcfg(B_, 256, 0);
        cudaLaunchKernelEx(&cfg, tail_kernel,
            (const float*)r3, b3, W4, b4, inputs, out, x,
            W1, b1, W2, b2, 0, 0, burn, 0);
    }

    for (int t = 0; t < NSTEP; t++) {
        // K_A2: gx = x(t)@Wih0 + biases (layer-0 h-part precomputed in prior comboA)
        {
            cudaLaunchConfig_t cfg = mkcfg(120, 256, SMEMB);
            cudaLaunchKernelEx(&cfg, gemm_single, gx, (int)G4_,
                (const __half*)x, (const __half*)wih, bih, bhh);
        }
        // cell0: gx + gh0(2 slices) -> c0, h0
        {
            cudaLaunchConfig_t cfg = mkcfg(240, 256, 0);
            cudaLaunchKernelEx(&cfg, lstm_cell,
                (const float*)gx, (const float*)gh0, c0, h0, 0);
        }
        // comboA: pooled {h0@Wih1 -> gx1, h0@Whh0 -> gh0 (for t+1)}
        {
            cudaLaunchConfig_t cfg = mkcfg(480, 256, SMEMB);
            cudaLaunchKernelEx(&cfg, gemm_comboA,
                (const __half*)h0, (const __half*)(wih + LOFF), (const __half*)whh,
                gx1, gh0, bih + G4_, bhh + G4_, (int)(t + 1 < NSTEP ? 1 : 0));
        }
        // cell1: gx1(2 slices) + gh1(2 slices) -> c1, h1
        {
            cudaLaunchConfig_t cfg = mkcfg(240, 256, 0);
            cudaLaunchKernelEx(&cfg, lstm_cell,
                (const float*)gx1, (const float*)gh1, c0 + B_ * H_, h1, 1);
        }
        // comboB: pooled {h1@Whh1 -> gh1 (for t+1), h1@W3 -> r3}
        {
            cudaLaunchConfig_t cfg = mkcfg(300, 256, SMEMB);
            cudaLaunchKernelEx(&cfg, gemm_comboB,
                (const __half*)h1, (const __half*)(whh + LOFF), (const __half*)w3,
                gh1, r3, (int)(t + 1 < NSTEP ? 1 : 0));
        }
        // tail: r3 slice-sum + bias/relu + W4 + residual + out, then MLP for t+1
        {
            cudaLaunchConfig_t cfg = mkcfg(B_, 256, 0);
            cudaLaunchKernelEx(&cfg, tail_kernel,
                (const float*)r3, b3, W4, b4, inputs, out, x,
                W1, b1, W2, b2, t, t + 1, burn, 1);
        }
    }
}

// round 16
// speedup vs baseline: 1.4737x; 1.0264x over previous
#include <cuda_runtime.h>
#include <cuda_fp16.h>
#include <cstdint>

// Problem constants
#define B_    128
#define A_    30
#define T_    65
#define FIN_  4
#define H_    1920
#define G4_   7680
#define NSTEP 64

// GEMM tiling: CTA tile 128(M) x 64(N), K chunk = 64 fp16
#define KCHUNKS  30                 // K chunks over full 1920
#define NSTG     4                  // pipeline stages
#define STAGE_B  24576              // A 16K + W 8K
#define SMEMB    (1024 + 1024 + NSTG * STAGE_B)
#define LOFF     14745600u          // per-layer elems in tiled LSTM weights
#define GSLICE   (B_ * G4_)         // one gates slice (floats)
#define TOT_IH   (2 * G4_ * H_)     // 29,491,200
#define TOT_W3   (H_ * H_)          // 3,686,400

// ---------------- device scratch (no allocation allowed) ----------------
__device__ __align__(1024) __half g_wih[2u*7680u*1920u];
__device__ __align__(1024) __half g_whh[2u*7680u*1920u];
__device__ __align__(1024) __half g_w3[1920u*1920u];
__device__ __align__(1024) __half g_x[245760];     // 30 chunks x 8192 (128 rows x 64 k)
__device__ __align__(1024) __half g_h0[245760];
__device__ __align__(1024) __half g_h1[245760];
__device__ float g_c[2 * B_ * H_];
__device__ float g_gx[GSLICE];                     // x@Wih0 (+biases), 1 slice
__device__ float g_gx1[2 * GSLICE];                // h0@Wih1 (+biases on s0), 2 K-slices
__device__ float g_gh0[2 * GSLICE];                // h0@Whh0, 2 K-slices
__device__ float g_gh1[2 * GSLICE];                // h1@Whh1, 2 K-slices
__device__ float g_r3[2 * B_ * H_];                // h1@W3, 2 K-slices

// ---------------- PTX helpers ----------------
__device__ __forceinline__ uint32_t smem_u32(const void* p) {
    uint32_t a;
    asm("{ .reg .u64 t; cvta.to.shared.u64 t, %1; cvt.u32.u64 %0, t; }" : "=r"(a) : "l"(p));
    return a;
}
#define MBAR_INIT(addr, cnt) \
    asm volatile("mbarrier.init.shared.b64 [%0], %1;" :: "r"(addr), "r"((uint32_t)(cnt)) : "memory")
#define MBAR_EXPECT_TX(addr, bytes) \
    asm volatile("mbarrier.arrive.expect_tx.shared.b64 _, [%0], %1;" :: "r"(addr), "r"((uint32_t)(bytes)) : "memory")
#define MBAR_ARRIVE(addr) \
    asm volatile("mbarrier.arrive.shared.b64 _, [%0];" :: "r"(addr) : "memory")
#define MBAR_WAIT(addr, par) do { \
    uint32_t _m=(addr), _p=(par), _d; \
    asm volatile("{\n\t.reg .pred p;\n\tmbarrier.try_wait.parity.acquire.cta.shared::cta.b64 p, [%1], %2;\n\tselp.b32 %0,1,0,p;\n\t}" \
        : "=r"(_d) : "r"(_m), "r"(_p) : "memory"); \
    if (!_d) { \
        asm volatile("{\n\t.reg .pred P1;\n\tWL_%=:\n\tmbarrier.try_wait.parity.acquire.cta.shared::cta.b64 P1, [%0], %1, 0x989680;\n\t@P1 bra.uni WD_%=;\n\tbra.uni WL_%=;\n\tWD_%=:\n\t}" \
            :: "r"(_m), "r"(_p) : "memory"); \
    } } while (0)
#define BULK_G2S(dst, src, bytes, mbar) \
    asm volatile("cp.async.bulk.shared::cluster.global.mbarrier::complete_tx::bytes [%0], [%1], %2, [%3];" \
        :: "r"(dst), "l"(src), "r"((uint32_t)(bytes)), "r"(mbar) : "memory")

#define LDSM4(r, addr) \
    asm volatile("ldmatrix.sync.aligned.m8n8.x4.shared.b16 {%0,%1,%2,%3}, [%4];" \
        : "=r"((r)[0]), "=r"((r)[1]), "=r"((r)[2]), "=r"((r)[3]) : "r"(addr))
#define MMA(d, a, b0v, b1v) \
    asm volatile("mma.sync.aligned.m16n8k16.row.col.f32.f16.f16.f32 " \
        "{%0,%1,%2,%3}, {%4,%5,%6,%7}, {%8,%9}, {%0,%1,%2,%3};" \
        : "+f"((d)[0]), "+f"((d)[1]), "+f"((d)[2]), "+f"((d)[3]) \
        : "r"((a)[0]), "r"((a)[1]), "r"((a)[2]), "r"((a)[3]), "r"(b0v), "r"(b1v))

__device__ __forceinline__ uint32_t sw128(uint32_t o) { return o ^ ((o >> 3) & 0x70); }
__device__ __forceinline__ uint32_t act_idx(int row, int k) {
    return (uint32_t)((k >> 6) * 8192) + (sw128((uint32_t)(row * 128 + (k & 63) * 2)) >> 1);
}

// ---------------- merged weight conversion ----------------
__global__ void __launch_bounds__(256) conv_all(
    const float* __restrict__ Wih, const float* __restrict__ Whh, const float* __restrict__ W3s,
    __half* __restrict__ wih, __half* __restrict__ whh, __half* __restrict__ w3)
{
    int i = blockIdx.x * 256 + threadIdx.x;
    const float* src; __half* dst; int local;
    if (i < TOT_IH)               { src = Wih; dst = wih; local = i; }
    else if (i < 2 * TOT_IH)      { src = Whh; dst = whh; local = i - TOT_IH; }
    else if (i < 2 * TOT_IH + TOT_W3) { src = W3s; dst = w3; local = i - 2 * TOT_IH; }
    else return;
    int n = local / H_, k = local - n * H_;
    uint32_t d = (uint32_t)((n >> 6) * KCHUNKS + (k >> 6)) * 4096
               + (sw128((uint32_t)((n & 63) * 128 + (k & 63) * 2)) >> 1);
    dst[d] = __float2half(src[local]);
}

// ---------------- GEMM core (device): W prefetched pre-PDL-sync, A post-sync ----------------
__device__ __forceinline__ void gemm_core(
    float* C, int ldc,
    const __half* A, const __half* W,
    const float* bias0, const float* bias1,
    int ccnt, int cbeg, int nt)
{
    extern __shared__ char smraw[];
    char* sm = (char*)(((unsigned long long)smraw + 1023ull) & ~1023ull);
    const uint32_t sb = smem_u32(sm);
    const uint32_t FULL = sb;
    const uint32_t DONE = sb + 64;
    const uint32_t STG0 = sb + 1024;

    const int tid = threadIdx.x;
    const int wid = tid >> 5, lane = tid & 31;
    const int wm = (wid & 3) * 32;
    const int wn = (wid >> 2) * 32;

    if (tid == 0) {
        for (int s = 0; s < NSTG; s++) { MBAR_INIT(FULL + 8 * s, 1); MBAR_INIT(DONE + 8 * s, 8); }
        asm volatile("fence.proxy.async.shared::cta;" ::: "memory");
    }
    __syncthreads();

    // prefetch W for the prologue stages BEFORE waiting on the predecessor (W is static)
    if (tid == 0) {
        for (int c = 0; c < NSTG && c < ccnt; c++) {
            int k = cbeg + c;
            uint32_t st = STG0 + c * STAGE_B;
            MBAR_EXPECT_TX(FULL + 8 * c, STAGE_B);
            BULK_G2S(st + 16384, W + ((size_t)nt * KCHUNKS + k) * 4096, 8192, FULL + 8 * c);
        }
    }

    cudaGridDependencySynchronize();

    // now fetch the dynamic A operand for the prologue stages
    if (tid == 0) {
        for (int c = 0; c < NSTG && c < ccnt; c++) {
            int k = cbeg + c;
            uint32_t st = STG0 + c * STAGE_B;
            BULK_G2S(st, A + (size_t)k * 8192, 16384, FULL + 8 * c);
        }
    }

    float acc[2][4][4];
#pragma unroll
    for (int i = 0; i < 2; i++)
#pragma unroll
        for (int jn = 0; jn < 4; jn++)
#pragma unroll
            for (int q = 0; q < 4; q++) acc[i][jn][q] = 0.f;

    const int a_row  = (lane & 7) + ((lane >> 3) & 1) * 8;
    const int a_koff = (lane >> 4) * 16;
    const int w_row  = (lane & 7) + ((lane >> 4) << 3);
    const int w_koff = ((lane >> 3) & 1) * 16;

    for (int c = 0; c < ccnt; c++) {
        int s = c & (NSTG - 1);
        MBAR_WAIT(FULL + 8 * s, (c >> 2) & 1);
        uint32_t stg = STG0 + s * STAGE_B;

#pragma unroll
        for (int kb = 0; kb < 4; kb++) {
            uint32_t av[2][4], wv[2][4];
#pragma unroll
            for (int mt = 0; mt < 2; mt++) {
                uint32_t ad = stg + sw128((uint32_t)((wm + mt * 16 + a_row) * 128 + kb * 32 + a_koff));
                LDSM4(av[mt], ad);
            }
#pragma unroll
            for (int hf = 0; hf < 2; hf++) {
                uint32_t wd = stg + 16384 + sw128((uint32_t)((wn + hf * 16 + w_row) * 128 + kb * 32 + w_koff));
                LDSM4(wv[hf], wd);
            }
#pragma unroll
            for (int mt = 0; mt < 2; mt++) {
#pragma unroll
                for (int hf = 0; hf < 2; hf++) {
                    MMA(acc[mt][2 * hf],     av[mt], wv[hf][0], wv[hf][1]);
                    MMA(acc[mt][2 * hf + 1], av[mt], wv[hf][2], wv[hf][3]);
                }
            }
        }
        __syncwarp();
        if (lane == 0) MBAR_ARRIVE(DONE + 8 * s);

        int ncn = c + NSTG;
        if (tid == 0 && ncn < ccnt) {
            MBAR_WAIT(DONE + 8 * s, (c >> 2) & 1);
            int k = cbeg + ncn;
            uint32_t st = STG0 + s * STAGE_B;
            MBAR_EXPECT_TX(FULL + 8 * s, STAGE_B);
            BULK_G2S(st,         A + (size_t)k * 8192, 16384, FULL + 8 * s);
            BULK_G2S(st + 16384, W + ((size_t)nt * KCHUNKS + k) * 4096, 8192, FULL + 8 * s);
        }
    }

#pragma unroll
    for (int mt = 0; mt < 2; mt++) {
        int r0 = wm + mt * 16 + (lane >> 2);
        float* cp = C + (size_t)r0 * ldc;
#pragma unroll
        for (int ng = 0; ng < 4; ng++) {
            int col = nt * 64 + wn + ng * 8 + 2 * (lane & 3);
            float b0v = 0.f, b1v = 0.f;
            if (bias0) { b0v = bias0[col] + bias1[col]; b1v = bias0[col + 1] + bias1[col + 1]; }
            *(float2*)(cp + col) = make_float2(acc[mt][ng][0] + b0v, acc[mt][ng][1] + b1v);
            *(float2*)(cp + 8 * ldc + col) = make_float2(acc[mt][ng][2] + b0v, acc[mt][ng][3] + b1v);
        }
    }
}

// ---------------- K_A2: x@Wih0 full-K with biases ----------------
__global__ void __launch_bounds__(256, 1) gemm_single(
    float* __restrict__ C, int ldc,
    const __half* __restrict__ A, const __half* __restrict__ W,
    const float* __restrict__ bias0, const float* __restrict__ bias1)
{
    gemm_core(C, ldc, A, W, bias0, bias1, KCHUNKS, 0, blockIdx.x);
}

// ---------------- comboA: {h0@Wih1 -> gx1 (240), h0@Whh0 -> gh0 (240)}, 480 CTAs x 15ch ----------------
__global__ void __launch_bounds__(256, 1) gemm_comboA(
    const __half* __restrict__ h0,
    const __half* __restrict__ wih1, const __half* __restrict__ whh0,
    float* __restrict__ gx1, float* __restrict__ gh0,
    const float* __restrict__ bih1, const float* __restrict__ bhh1,
    int doGh)
{
    int bid = blockIdx.x;
    if (bid < 240) {
        int slice = bid / 120, nt = bid - slice * 120;
        const float* b0 = (slice == 0) ? bih1 : nullptr;
        const float* b1 = (slice == 0) ? bhh1 : nullptr;
        gemm_core(gx1 + (size_t)slice * GSLICE, G4_, h0, wih1, b0, b1, 15, slice * 15, nt);
    } else {
        if (!doGh) return;
        int b = bid - 240;
        int slice = b / 120, nt = b - slice * 120;
        gemm_core(gh0 + (size_t)slice * GSLICE, G4_, h0, whh0, nullptr, nullptr, 15, slice * 15, nt);
    }
}

// ---------------- comboB: {h1@Whh1 -> gh1 (240), h1@W3 -> r3 (60)}, 300 CTAs x 15ch ----------------
__global__ void __launch_bounds__(256, 1) gemm_comboB(
    const __half* __restrict__ h1,
    const __half* __restrict__ whh1, const __half* __restrict__ w3,
    float* __restrict__ gh1, float* __restrict__ r3, int doGh)
{
    int bid = blockIdx.x;
    if (bid < 240) {
        if (!doGh) return;
        int slice = bid / 120, nt = bid - slice * 120;
        gemm_core(gh1 + (size_t)slice * GSLICE, G4_, h1, whh1, nullptr, nullptr, 15, slice * 15, nt);
    } else {
        int b = bid - 240;
        int slice = b / 30, nt = b - slice * 30;
        gemm_core(r3 + (size_t)slice * B_ * H_, H_, h1, w3, nullptr, nullptr, 15, slice * 15, nt);
    }
}

// ---------------- LSTM cell: x2 vectorized, 480 blocks (higher TLP) ----------------
__global__ void __launch_bounds__(256) lstm_cell(
    const float* __restrict__ gx, const float* __restrict__ gh,
    float* __restrict__ c, __half* __restrict__ h, int twoGx)
{
    cudaGridDependencySynchronize();
    int idx2 = (blockIdx.x * 256 + threadIdx.x) * 2;   // < 128*1920, 480 blocks
    int b = idx2 / H_;
    int jj = idx2 - b * H_;                            // jj % 2 == 0
    const float* px = gx + b * G4_;
    const float* px2 = gx + GSLICE + b * G4_;
    const float* p0 = gh + b * G4_;
    const float* p1 = gh + GSLICE + b * G4_;

    float igs[2], fgs[2], ggs[2], ogs[2];
    {
        float2 xi = *(const float2*)(px + jj),           hi0 = *(const float2*)(p0 + jj),           hi1 = *(const float2*)(p1 + jj);
        float2 xf = *(const float2*)(px + H_ + jj),      hf0 = *(const float2*)(p0 + H_ + jj),      hf1 = *(const float2*)(p1 + H_ + jj);
        float2 xg = *(const float2*)(px + 2 * H_ + jj),  hg0 = *(const float2*)(p0 + 2 * H_ + jj),  hg1 = *(const float2*)(p1 + 2 * H_ + jj);
        float2 xo = *(const float2*)(px + 3 * H_ + jj),  ho0 = *(const float2*)(p0 + 3 * H_ + jj),  ho1 = *(const float2*)(p1 + 3 * H_ + jj);
        igs[0] = xi.x + hi0.x + hi1.x; igs[1] = xi.y + hi0.y + hi1.y;
        fgs[0] = xf.x + hf0.x + hf1.x; fgs[1] = xf.y + hf0.y + hf1.y;
        ggs[0] = xg.x + hg0.x + hg1.x; ggs[1] = xg.y + hg0.y + hg1.y;
        ogs[0] = xo.x + ho0.x + ho1.x; ogs[1] = xo.y + ho0.y + ho1.y;
    }
    if (twoGx) {
        float2 xi = *(const float2*)(px2 + jj);
        float2 xf = *(const float2*)(px2 + H_ + jj);
        float2 xg = *(const float2*)(px2 + 2 * H_ + jj);
        float2 xo = *(const float2*)(px2 + 3 * H_ + jj);
        igs[0] += xi.x; igs[1] += xi.y;
        fgs[0] += xf.x; fgs[1] += xf.y;
        ggs[0] += xg.x; ggs[1] += xg.y;
        ogs[0] += xo.x; ogs[1] += xo.y;
    }
    float2 cv = *(const float2*)(c + idx2);
    float cvs[2] = { cv.x, cv.y };
    float hn[2], cn[2];
#pragma unroll
    for (int q = 0; q < 2; q++) {
        float si = 1.f / (1.f + expf(-igs[q]));
        float sf = 1.f / (1.f + expf(-fgs[q]));
        float so = 1.f / (1.f + expf(-ogs[q]));
        float tg = tanhf(ggs[q]);
        cn[q] = sf * cvs[q] + si * tg;
        hn[q] = so * tanhf(cn[q]);
    }
    *(float2*)(c + idx2) = make_float2(cn[0], cn[1]);

    __half2 a2 = __floats2half2_rn(hn[0], hn[1]);
    uint32_t byteoff = (uint32_t)(jj >> 6) * 16384 + sw128((uint32_t)(b * 128 + (jj & 63) * 2));
    *(uint32_t*)((char*)h + byteoff) = *(uint32_t*)&a2;
}

// ---------------- tail (256 thr): r3 sum + W4 (split dots) + residual + out, then MLP ----------------
__global__ void __launch_bounds__(256) tail_kernel(
    const float* __restrict__ r3, const float* __restrict__ b3,
    const float* __restrict__ W4, const float* __restrict__ b4,
    const float* __restrict__ inputs, float* __restrict__ out,
    __half* __restrict__ x,
    const float* __restrict__ W1, const float* __restrict__ b1,
    const float* __restrict__ W2, const float* __restrict__ b2,
    int t, int produce, const int* __restrict__ burn, int do_w4)
{
    __shared__ __align__(16) float xs[H_];
    __shared__ float part[240];
    __shared__ float outs[A_ * FIN_];
    __shared__ float W1t[4 * 64];
    __shared__ float W2t[64 * 64];
    __shared__ float b1s[64], b2s[64];
    __shared__ float ins_s[A_ * FIN_];
    __shared__ float x1s[A_ * 64];

    const int b = blockIdx.x, tid = threadIdx.x;

    // dependency-free: stage MLP weights
    for (int i = tid; i < 64 * 64; i += 256) {
        int jj = i >> 6, kk = i & 63;
        W2t[kk * 64 + jj] = W2[i];
    }
    if (tid < 256) {
        int jj = tid >> 2, ff = tid & 3;
        W1t[ff * 64 + jj] = W1[tid];
    }
    if (tid < 64) { b1s[tid] = b1[tid]; b2s[tid] = b2[tid]; }

    cudaGridDependencySynchronize();
    const int bi = burn ? *burn : 20;

    if (do_w4) {
        for (int k = tid; k < H_; k += 256)
            xs[k] = fmaxf(r3[b * H_ + k] + r3[(B_ + b) * H_ + k] + b3[k], 0.f);
        __syncthreads();
        if (tid < 240) {
            int o = tid % 120, half = tid / 120;
            const float4* wp = (const float4*)(W4 + (size_t)o * H_ + half * 960);
            const float4* xp = (const float4*)(xs + half * 960);
            float a0 = 0.f, a1 = 0.f, a2 = 0.f, a3 = 0.f;
#pragma unroll 4
            for (int k = 0; k < 240; k++) {
                float4 w = wp[k]; float4 xv = xp[k];
                a0 = fmaf(w.x, xv.x, a0); a1 = fmaf(w.y, xv.y, a1);
                a2 = fmaf(w.z, xv.z, a2); a3 = fmaf(w.w, xv.w, a3);
            }
            part[tid] = (a0 + a1) + (a2 + a3);
        }
        __syncthreads();
        if (tid < A_ * FIN_) {
            float acc = b4[tid] + part[tid] + part[tid + 120];
            int a = tid >> 2, f = tid & 3;
            int r = b * A_ + a;
            float insv = (t <= bi) ? inputs[(r * T_ + t) * FIN_ + f]
                                   : out[(r * NSTEP + t - 1) * FIN_ + f];
            float ov = acc + insv;
            out[(r * NSTEP + t) * FIN_ + f] = ov;
            outs[tid] = ov;
        }
        __syncthreads();
    }

    if (produce >= NSTEP) return;

    if (tid < A_ * FIN_) {
        int a = tid >> 2, f = tid & 3;
        int r = b * A_ + a;
        ins_s[tid] = (produce <= bi) ? inputs[(r * T_ + produce) * FIN_ + f] : outs[tid];
    }
    __syncthreads();

    for (int idx = tid; idx < A_ * 64; idx += 256) {
        int a = idx >> 6, j = idx & 63;
        float v = b1s[j];
#pragma unroll
        for (int f = 0; f < 4; f++) v = fmaf(ins_s[a * 4 + f], W1t[f * 64 + j], v);
        x1s[idx] = fmaxf(v, 0.f);
    }
    __syncthreads();

    for (int idx = tid; idx < A_ * 64; idx += 256) {
        int a = idx >> 6, j = idx & 63;
        float v = b2s[j];
        const float* x1p = x1s + a * 64;
#pragma unroll
        for (int k = 0; k < 64; k++) v = fmaf(x1p[k], W2t[k * 64 + j], v);
        v = fmaxf(v, 0.f);
        x[act_idx(b, a * 64 + j)] = __float2half(v);
    }
}

// ---------------- launch ----------------
extern "C" void kernel_launch(void* const* d_in, const int* in_sizes, int n_in,
                              void* d_out, int out_size)
{
    const float* inputs = (const float*)d_in[0];
    const float* W1  = (const float*)d_in[1];
    const float* b1  = (const float*)d_in[2];
    const float* W2  = (const float*)d_in[3];
    const float* b2  = (const float*)d_in[4];
    const float* Wih = (const float*)d_in[5];
    const float* Whh = (const float*)d_in[6];
    const float* bih = (const float*)d_in[7];
    const float* bhh = (const float*)d_in[8];
    const float* W3  = (const float*)d_in[9];
    const float* b3  = (const float*)d_in[10];
    const float* W4  = (const float*)d_in[11];
    const float* b4  = (const float*)d_in[12];
    const int* burn  = (n_in > 14) ? (const int*)d_in[14] : nullptr;
    float* out = (float*)d_out;

    cudaFuncSetAttribute(gemm_single, cudaFuncAttributeMaxDynamicSharedMemorySize, SMEMB);
    cudaFuncSetAttribute(gemm_comboA, cudaFuncAttributeMaxDynamicSharedMemorySize, SMEMB);
    cudaFuncSetAttribute(gemm_comboB, cudaFuncAttributeMaxDynamicSharedMemorySize, SMEMB);

    void *pwih, *pwhh, *pw3, *px, *ph0, *ph1, *pc, *pgx, *pgx1, *pgh0, *pgh1, *pr;
    cudaGetSymbolAddress(&pwih, g_wih);
    cudaGetSymbolAddress(&pwhh, g_whh);
    cudaGetSymbolAddress(&pw3, g_w3);
    cudaGetSymbolAddress(&px, g_x);
    cudaGetSymbolAddress(&ph0, g_h0);
    cudaGetSymbolAddress(&ph1, g_h1);
    cudaGetSymbolAddress(&pc, g_c);
    cudaGetSymbolAddress(&pgx, g_gx);
    cudaGetSymbolAddress(&pgx1, g_gx1);
    cudaGetSymbolAddress(&pgh0, g_gh0);
    cudaGetSymbolAddress(&pgh1, g_gh1);
    cudaGetSymbolAddress(&pr, g_r3);

    __half *wih = (__half*)pwih, *whh = (__half*)pwhh, *w3 = (__half*)pw3;
    __half *x = (__half*)px, *h0 = (__half*)ph0, *h1 = (__half*)ph1;
    float* c0 = (float*)pc;
    float* gx = (float*)pgx;
    float* gx1 = (float*)pgx1;
    float* gh0 = (float*)pgh0;
    float* gh1 = (float*)pgh1;
    float* r3 = (float*)pr;

    // zero recurrent state + h-part gate slices (h=0 at t=0)
    cudaMemsetAsync(pc, 0, sizeof(float) * 2 * B_ * H_);
    cudaMemsetAsync(ph0, 0, sizeof(__half) * 245760);
    cudaMemsetAsync(ph1, 0, sizeof(__half) * 245760);
    cudaMemsetAsync(pgh0, 0, sizeof(float) * 2 * GSLICE);
    cudaMemsetAsync(pgh1, 0, sizeof(float) * 2 * GSLICE);

    // PDL launch config
    cudaLaunchAttribute pdlAttr[1];
    pdlAttr[0].id = cudaLaunchAttributeProgrammaticStreamSerialization;
    pdlAttr[0].val.programmaticStreamSerializationAllowed = 1;
    auto mkcfg = [&](unsigned grid, unsigned block, size_t smem) {
        cudaLaunchConfig_t cfg = {};
        cfg.gridDim = dim3(grid, 1, 1);
        cfg.blockDim = dim3(block, 1, 1);
        cfg.dynamicSmemBytes = smem;
        cfg.stream = 0;
        cfg.attrs = pdlAttr;
        cfg.numAttrs = 1;
        return cfg;
    };

    const int TOTAL_CONV = 2 * TOT_IH + TOT_W3;
    conv_all<<<(TOTAL_CONV + 255) / 256, 256>>>(Wih, Whh, W3, wih, whh, w3);

    // initial MLP (produce x for t=0)
    {
        cudaLaunchConfig_t cfg = mkcfg(B_, 256, 0);
        cudaLaunchKernelEx(&cfg, tail_kernel,
            (const float*)r3, b3, W4, b4, inputs, out, x,
            W1, b1, W2, b2, 0, 0, burn, 0);
    }

    for (int t = 0; t < NSTEP; t++) {
        // K_A2: gx = x(t)@Wih0 + biases (layer-0 h-part precomputed in prior comboA)
        {
            cudaLaunchConfig_t cfg = mkcfg(120, 256, SMEMB);
            cudaLaunchKernelEx(&cfg, gemm_single, gx, (int)G4_,
                (const __half*)x, (const __half*)wih, bih, bhh);
        }
        // cell0: gx + gh0(2 slices) -> c0, h0
        {
            cudaLaunchConfig_t cfg = mkcfg(480, 256, 0);
            cudaLaunchKernelEx(&cfg, lstm_cell,
                (const float*)gx, (const float*)gh0, c0, h0, 0);
        }
        // comboA: pooled {h0@Wih1 -> gx1, h0@Whh0 -> gh0 (for t+1)}
        {
            cudaLaunchConfig_t cfg = mkcfg(480, 256, SMEMB);
            cudaLaunchKernelEx(&cfg, gemm_comboA,
                (const __half*)h0, (const __half*)(wih + LOFF), (const __half*)whh,
                gx1, gh0, bih + G4_, bhh + G4_, (int)(t + 1 < NSTEP ? 1 : 0));
        }
        // cell1: gx1(2 slices) + gh1(2 slices) -> c1, h1
        {
            cudaLaunchConfig_t cfg = mkcfg(480, 256, 0);
            cudaLaunchKernelEx(&cfg, lstm_cell,
                (const float*)gx1, (const float*)gh1, c0 + B_ * H_, h1, 1);
        }
        // comboB: pooled {h1@Whh1 -> gh1 (for t+1), h1@W3 -> r3}
        {
            cudaLaunchConfig_t cfg = mkcfg(300, 256, SMEMB);
            cudaLaunchKernelEx(&cfg, gemm_comboB,
                (const __half*)h1, (const __half*)(whh + LOFF), (const __half*)w3,
                gh1, r3, (int)(t + 1 < NSTEP ? 1 : 0));
        }
        // tail: r3 slice-sum + bias/relu + W4 + residual + out, then MLP for t+1
        {
            cudaLaunchConfig_t cfg = mkcfg(B_, 256, 0);
            cudaLaunchKernelEx(&cfg, tail_kernel,
                (const float*)r3, b3, W4, b4, inputs, out, x,
                W1, b1, W2, b2, t, t + 1, burn, 1);
        }
    }
}